// round 1
// baseline (speedup 1.0000x reference)
#include <cuda_runtime.h>
#include <math.h>

// ---------------- problem constants ----------------
#define FULLMASK 0xffffffffu
static const int   T_LEN  = 256;
static const int   C_DIM  = 512;
static const long  M_ROWS = 81920;          // 32*10*256
static const float EPS_F  = 1e-5f;
static const float ATT_SCALE = 0.08838834764831845f;  // 128^-0.5

// ---------------- scratch (device globals; no allocation) ----------------
__device__ float g_h  [81920L*512];
__device__ float g_u  [81920L*512];
__device__ float g_qkv[81920L*1536];
__device__ float g_att[81920L*512];
__device__ float g_mlp[81920L*512];
__device__ float g_S  [1280L*256*256];
__device__ float g_Wc [3L*1024*512];
__device__ float g_d1 [81920];
__device__ float g_d2 [81920];
__device__ float g_sc [81920];

// ---------------- helpers ----------------
__device__ __forceinline__ float gelu_exact(float v) {
    return 0.5f * v * (1.0f + erff(v * 0.70710678118654752f));
}
__device__ __forceinline__ float warp_sum(float v) {
    #pragma unroll
    for (int o = 16; o > 0; o >>= 1) v += __shfl_xor_sync(FULLMASK, v, o);
    return v;
}
__device__ __forceinline__ float warp_max(float v) {
    #pragma unroll
    for (int o = 16; o > 0; o >>= 1) v = fmaxf(v, __shfl_xor_sync(FULLMASK, v, o));
    return v;
}

// ---------------- W_emb transpose: (C,D,3) -> (3,D,C) for coalesced GEMM B ----------------
__global__ void prep_w_kernel(const float* __restrict__ W, float* __restrict__ Wc) {
    int i = blockIdx.x * blockDim.x + threadIdx.x;
    if (i >= 3 * 1024 * 512) return;
    int c = i & 511;
    int d = (i >> 9) & 1023;
    int k = i >> 19;
    Wc[i] = W[(long)c * 3072 + d * 3 + k];
}

// ---------------- generic NN SGEMM 128x128x8, 8x8 microtile ----------------
// C[r,c] = act( beta*C + A@B + bias ).  pv==1: batched attention-PV offsets.
__global__ __launch_bounds__(256) void sgemm_nn(
    const float* __restrict__ A, const float* __restrict__ B,
    const float* __restrict__ bias, float* __restrict__ C,
    int K, int lda, int ldb, int ldc,
    long sA, long sB, long sC, int addC, int act, int pv)
{
    __shared__ float As[8][128];
    __shared__ float Bs[8][128];
    int tid = threadIdx.x;
    int z = blockIdx.z;
    long oA, oB, oC;
    if (!pv) { oA = (long)z * sA; oB = (long)z * sB; oC = (long)z * sC; }
    else {
        int bn = z >> 2, hd = z & 3;
        oA = (long)z * 65536;
        oB = (long)bn * (256L * 1536) + 1024 + hd * 128;
        oC = (long)bn * (256L * 512) + hd * 128;
    }
    int aRow = tid >> 1, aCol = (tid & 1) * 4;
    int bRow = tid >> 5, bCol = (tid & 31) * 4;
    int ty = tid >> 4, tx = tid & 15;
    const float* Ag = A + oA + (long)(blockIdx.y * 128 + aRow) * lda + aCol;
    const float* Bg = B + oB + (long)bRow * ldb + blockIdx.x * 128 + bCol;

    float acc[8][8];
    #pragma unroll
    for (int i = 0; i < 8; i++)
        #pragma unroll
        for (int j = 0; j < 8; j++) acc[i][j] = 0.f;

    for (int k0 = 0; k0 < K; k0 += 8) {
        float4 a4 = *(const float4*)(Ag + k0);
        float4 b4 = *(const float4*)(Bg + (long)k0 * ldb);
        __syncthreads();
        As[aCol + 0][aRow] = a4.x; As[aCol + 1][aRow] = a4.y;
        As[aCol + 2][aRow] = a4.z; As[aCol + 3][aRow] = a4.w;
        *(float4*)&Bs[bRow][bCol] = b4;
        __syncthreads();
        #pragma unroll
        for (int kk = 0; kk < 8; kk++) {
            float ra[8], rb[8];
            *(float4*)(ra)     = *(const float4*)&As[kk][ty * 4];
            *(float4*)(ra + 4) = *(const float4*)&As[kk][64 + ty * 4];
            *(float4*)(rb)     = *(const float4*)&Bs[kk][tx * 4];
            *(float4*)(rb + 4) = *(const float4*)&Bs[kk][64 + tx * 4];
            #pragma unroll
            for (int i = 0; i < 8; i++)
                #pragma unroll
                for (int j = 0; j < 8; j++)
                    acc[i][j] = fmaf(ra[i], rb[j], acc[i][j]);
        }
    }

    float* Cg = C + oC;
    #pragma unroll
    for (int i = 0; i < 8; i++) {
        int r = blockIdx.y * 128 + ((i < 4) ? (ty * 4 + i) : (64 + ty * 4 + i - 4));
        #pragma unroll
        for (int jb = 0; jb < 2; jb++) {
            int c = blockIdx.x * 128 + ((jb == 0) ? (tx * 4) : (64 + tx * 4));
            float4 v = make_float4(acc[i][jb * 4 + 0], acc[i][jb * 4 + 1],
                                   acc[i][jb * 4 + 2], acc[i][jb * 4 + 3]);
            if (bias) {
                float4 bb = *(const float4*)(bias + c);
                v.x += bb.x; v.y += bb.y; v.z += bb.z; v.w += bb.w;
            }
            if (addC) {
                float4 ov = *(const float4*)&Cg[(long)r * ldc + c];
                v.x += ov.x; v.y += ov.y; v.z += ov.z; v.w += ov.w;
            }
            if (act == 1) {
                v.x = fmaxf(v.x, 0.f); v.y = fmaxf(v.y, 0.f);
                v.z = fmaxf(v.z, 0.f); v.w = fmaxf(v.w, 0.f);
            } else if (act == 2) {
                v.x = gelu_exact(v.x); v.y = gelu_exact(v.y);
                v.z = gelu_exact(v.z); v.w = gelu_exact(v.w);
            }
            *(float4*)&Cg[(long)r * ldc + c] = v;
        }
    }
}

// ---------------- conv1d(k=3,pad=1) as GEMM with 3 shifted K-passes ----------------
__global__ __launch_bounds__(256) void conv_embed(
    const float* __restrict__ x, const float* __restrict__ Wc,
    const float* __restrict__ bias, float* __restrict__ out)
{
    __shared__ float As[8][128];
    __shared__ float Bs[8][128];
    int tid = threadIdx.x;
    int bm = blockIdx.y * 128, bn0 = blockIdx.x * 128;
    int aRow = tid >> 1, aCol = (tid & 1) * 4;
    int bRow = tid >> 5, bCol = (tid & 31) * 4;
    int ty = tid >> 4, tx = tid & 15;
    int row = bm + aRow;
    int t = row & 255;

    float acc[8][8];
    #pragma unroll
    for (int i = 0; i < 8; i++)
        #pragma unroll
        for (int j = 0; j < 8; j++) acc[i][j] = 0.f;

    for (int k = 0; k < 3; k++) {
        int shift = k - 1;
        bool valid = ((unsigned)(t + shift)) < 256u;
        const float* Ag = x + (long)(row + shift) * 1024 + aCol;
        const float* Bg = Wc + (long)k * (1024L * 512) + (long)bRow * 512 + bn0 + bCol;
        for (int k0 = 0; k0 < 1024; k0 += 8) {
            float4 a4 = make_float4(0.f, 0.f, 0.f, 0.f);
            if (valid) a4 = *(const float4*)(Ag + k0);
            float4 b4 = *(const float4*)(Bg + (long)k0 * 512);
            __syncthreads();
            As[aCol + 0][aRow] = a4.x; As[aCol + 1][aRow] = a4.y;
            As[aCol + 2][aRow] = a4.z; As[aCol + 3][aRow] = a4.w;
            *(float4*)&Bs[bRow][bCol] = b4;
            __syncthreads();
            #pragma unroll
            for (int kk = 0; kk < 8; kk++) {
                float ra[8], rb[8];
                *(float4*)(ra)     = *(const float4*)&As[kk][ty * 4];
                *(float4*)(ra + 4) = *(const float4*)&As[kk][64 + ty * 4];
                *(float4*)(rb)     = *(const float4*)&Bs[kk][tx * 4];
                *(float4*)(rb + 4) = *(const float4*)&Bs[kk][64 + tx * 4];
                #pragma unroll
                for (int i = 0; i < 8; i++)
                    #pragma unroll
                    for (int j = 0; j < 8; j++)
                        acc[i][j] = fmaf(ra[i], rb[j], acc[i][j]);
            }
        }
    }

    #pragma unroll
    for (int i = 0; i < 8; i++) {
        int r = bm + ((i < 4) ? (ty * 4 + i) : (64 + ty * 4 + i - 4));
        #pragma unroll
        for (int jb = 0; jb < 2; jb++) {
            int c = bn0 + ((jb == 0) ? (tx * 4) : (64 + tx * 4));
            float4 bb = *(const float4*)(bias + c);
            float4 v = make_float4(fmaxf(acc[i][jb*4+0] + bb.x, 0.f),
                                   fmaxf(acc[i][jb*4+1] + bb.y, 0.f),
                                   fmaxf(acc[i][jb*4+2] + bb.z, 0.f),
                                   fmaxf(acc[i][jb*4+3] + bb.w, 0.f));
            *(float4*)&out[(long)r * 512 + c] = v;
        }
    }
}

// ---------------- attention scores: S = Q K^T * scale (batched over bn*heads) ----------------
__global__ __launch_bounds__(256) void attn_scores(const float* __restrict__ qkv,
                                                   float* __restrict__ S)
{
    __shared__ float As[8][128];
    __shared__ float Bs[8][128];
    int tid = threadIdx.x;
    int z = blockIdx.z;
    int bn = z >> 2, hd = z & 3;
    const float* Qb = qkv + (long)bn * (256L * 1536) + hd * 128;
    const float* Kb = Qb + 512;
    int aRow = tid >> 1, aCol = (tid & 1) * 4;
    int ty = tid >> 4, tx = tid & 15;
    const float* Ag = Qb + (long)(blockIdx.y * 128 + aRow) * 1536 + aCol;
    const float* Bg = Kb + (long)(blockIdx.x * 128 + aRow) * 1536 + aCol;

    float acc[8][8];
    #pragma unroll
    for (int i = 0; i < 8; i++)
        #pragma unroll
        for (int j = 0; j < 8; j++) acc[i][j] = 0.f;

    for (int k0 = 0; k0 < 128; k0 += 8) {
        float4 a4 = *(const float4*)(Ag + k0);
        float4 b4 = *(const float4*)(Bg + k0);
        __syncthreads();
        As[aCol + 0][aRow] = a4.x; As[aCol + 1][aRow] = a4.y;
        As[aCol + 2][aRow] = a4.z; As[aCol + 3][aRow] = a4.w;
        Bs[aCol + 0][aRow] = b4.x; Bs[aCol + 1][aRow] = b4.y;
        Bs[aCol + 2][aRow] = b4.z; Bs[aCol + 3][aRow] = b4.w;
        __syncthreads();
        #pragma unroll
        for (int kk = 0; kk < 8; kk++) {
            float ra[8], rb[8];
            *(float4*)(ra)     = *(const float4*)&As[kk][ty * 4];
            *(float4*)(ra + 4) = *(const float4*)&As[kk][64 + ty * 4];
            *(float4*)(rb)     = *(const float4*)&Bs[kk][tx * 4];
            *(float4*)(rb + 4) = *(const float4*)&Bs[kk][64 + tx * 4];
            #pragma unroll
            for (int i = 0; i < 8; i++)
                #pragma unroll
                for (int j = 0; j < 8; j++)
                    acc[i][j] = fmaf(ra[i], rb[j], acc[i][j]);
        }
    }

    float* Sg = S + (long)z * 65536;
    #pragma unroll
    for (int i = 0; i < 8; i++) {
        int r = blockIdx.y * 128 + ((i < 4) ? (ty * 4 + i) : (64 + ty * 4 + i - 4));
        #pragma unroll
        for (int jb = 0; jb < 2; jb++) {
            int c = blockIdx.x * 128 + ((jb == 0) ? (tx * 4) : (64 + tx * 4));
            float4 v = make_float4(acc[i][jb*4+0] * ATT_SCALE, acc[i][jb*4+1] * ATT_SCALE,
                                   acc[i][jb*4+2] * ATT_SCALE, acc[i][jb*4+3] * ATT_SCALE);
            *(float4*)&Sg[(long)r * 256 + c] = v;
        }
    }
}

// ---------------- row softmax over 256 (warp per row) ----------------
__global__ __launch_bounds__(256) void softmax_rows(float* __restrict__ S) {
    long row = (long)blockIdx.x * 8 + (threadIdx.x >> 5);
    int lane = threadIdx.x & 31;
    float* p = S + row * 256 + lane * 8;
    float4 v0 = *(float4*)p;
    float4 v1 = *(float4*)(p + 4);
    float m = fmaxf(fmaxf(fmaxf(v0.x, v0.y), fmaxf(v0.z, v0.w)),
                    fmaxf(fmaxf(v1.x, v1.y), fmaxf(v1.z, v1.w)));
    m = warp_max(m);
    v0.x = __expf(v0.x - m); v0.y = __expf(v0.y - m);
    v0.z = __expf(v0.z - m); v0.w = __expf(v0.w - m);
    v1.x = __expf(v1.x - m); v1.y = __expf(v1.y - m);
    v1.z = __expf(v1.z - m); v1.w = __expf(v1.w - m);
    float s = v0.x + v0.y + v0.z + v0.w + v1.x + v1.y + v1.z + v1.w;
    s = warp_sum(s);
    float inv = 1.0f / s;
    v0.x *= inv; v0.y *= inv; v0.z *= inv; v0.w *= inv;
    v1.x *= inv; v1.y *= inv; v1.z *= inv; v1.w *= inv;
    *(float4*)p = v0;
    *(float4*)(p + 4) = v1;
}

// ---------------- layernorm over 512 (warp per row) ----------------
__global__ __launch_bounds__(256) void layernorm_k(
    const float* __restrict__ in, float* __restrict__ out,
    const float* __restrict__ g, const float* __restrict__ b)
{
    long row = (long)blockIdx.x * 8 + (threadIdx.x >> 5);
    int lane = threadIdx.x & 31;
    const float* p = in + row * 512;
    float4 v[4];
    float s = 0.f, sq = 0.f;
    #pragma unroll
    for (int i = 0; i < 4; i++) {
        v[i] = *(const float4*)(p + i * 128 + lane * 4);
        s += v[i].x + v[i].y + v[i].z + v[i].w;
        sq = fmaf(v[i].x, v[i].x, sq); sq = fmaf(v[i].y, v[i].y, sq);
        sq = fmaf(v[i].z, v[i].z, sq); sq = fmaf(v[i].w, v[i].w, sq);
    }
    s = warp_sum(s); sq = warp_sum(sq);
    float mu = s * (1.0f / 512.0f);
    float var = sq * (1.0f / 512.0f) - mu * mu;
    float inv = rsqrtf(var + EPS_F);
    float* q = out + row * 512;
    #pragma unroll
    for (int i = 0; i < 4; i++) {
        int c = i * 128 + lane * 4;
        float4 gg = *(const float4*)(g + c);
        float4 bb = *(const float4*)(b + c);
        float4 o;
        o.x = (v[i].x - mu) * inv * gg.x + bb.x;
        o.y = (v[i].y - mu) * inv * gg.y + bb.y;
        o.z = (v[i].z - mu) * inv * gg.z + bb.z;
        o.w = (v[i].w - mu) * inv * gg.w + bb.w;
        *(float4*)(q + c) = o;
    }
}

// ---------------- fused NormalHead: c1->bn1->relu->c2->bn2->relu->c3->sigmoid + d1,d2 ----------------
__global__ __launch_bounds__(256) void head_kernel(
    const float* __restrict__ h,
    const float* __restrict__ c1W, const float* __restrict__ c1b,
    const float* __restrict__ bn1g, const float* __restrict__ bn1b,
    const float* __restrict__ bn1rm, const float* __restrict__ bn1rv,
    const float* __restrict__ c2W, const float* __restrict__ c2b,
    const float* __restrict__ bn2g, const float* __restrict__ bn2b,
    const float* __restrict__ bn2rm, const float* __restrict__ bn2rv,
    const float* __restrict__ c3W, const float* __restrict__ c3b,
    float* __restrict__ d1, float* __restrict__ d2, float* __restrict__ sc)
{
    long row = (long)blockIdx.x * 8 + (threadIdx.x >> 5);
    int lane = threadIdx.x & 31;
    const float* hr = h + row * 512;
    const float* w = c1W + lane * 512;
    float acc1 = 0.f;
    #pragma unroll 4
    for (int c0 = 0; c0 < 512; c0 += 4) {
        float4 hv = *(const float4*)(hr + c0);
        float4 wv = *(const float4*)(w + c0);
        acc1 = fmaf(hv.x, wv.x, acc1); acc1 = fmaf(hv.y, wv.y, acc1);
        acc1 = fmaf(hv.z, wv.z, acc1); acc1 = fmaf(hv.w, wv.w, acc1);
    }
    float x1 = acc1 + c1b[lane];

    // d1 = sqrt(sum (x1-rm1)^2 / rv1)   (raw rv, no eps)
    float rm1 = bn1rm[lane], rv1 = bn1rv[lane];
    float dd1 = (x1 - rm1) * (x1 - rm1) / rv1;
    dd1 = warp_sum(dd1);
    // bn1 eval + relu
    float y1 = fmaxf((x1 - rm1) * rsqrtf(rv1 + EPS_F) * bn1g[lane] + bn1b[lane], 0.f);

    // x2 = y1 @ c2W^T + c2b (lanes 0..15 hold outputs)
    float acc2 = (lane < 16) ? c2b[lane] : 0.f;
    #pragma unroll
    for (int i = 0; i < 32; i++) {
        float y1i = __shfl_sync(FULLMASK, y1, i);
        float w2 = (lane < 16) ? c2W[lane * 32 + i] : 0.f;
        acc2 = fmaf(y1i, w2, acc2);
    }
    float x2 = acc2;

    float rm2 = (lane < 16) ? bn2rm[lane] : 0.f;
    float rv2 = (lane < 16) ? bn2rv[lane] : 1.f;
    float dd2 = (lane < 16) ? (x2 - rm2) * (x2 - rm2) / rv2 : 0.f;
    dd2 = warp_sum(dd2);

    float y2 = 0.f;
    if (lane < 16)
        y2 = fmaxf((x2 - rm2) * rsqrtf(rv2 + EPS_F) * bn2g[lane] + bn2b[lane], 0.f);
    float sp = (lane < 16) ? y2 * c3W[lane] : 0.f;
    sp = warp_sum(sp);
    float score = 1.0f / (1.0f + __expf(-(sp + c3b[0])));

    if (lane == 0) {
        d1[row] = sqrtf(dd1);
        d2[row] = sqrtf(dd2);
        sc[row] = score;
    }
}

// ---------------- final reduce over n: out[b,t] = (mean d1 + mean d2)*mean sc ----------------
__global__ void final_kernel(const float* __restrict__ d1, const float* __restrict__ d2,
                             const float* __restrict__ sc, float* __restrict__ out)
{
    int idx = blockIdx.x * blockDim.x + threadIdx.x;
    if (idx >= 8192) return;
    int b = idx >> 8, t = idx & 255;
    float s1 = 0.f, s2 = 0.f, s3 = 0.f;
    #pragma unroll
    for (int n = 0; n < 10; n++) {
        long m = ((long)(b * 10 + n)) * 256 + t;
        s1 += d1[m]; s2 += d2[m]; s3 += sc[m];
    }
    out[idx] = (s1 + s2) * 0.1f * (s3 * 0.1f);
}

// ---------------- launch ----------------
extern "C" void kernel_launch(void* const* d_in, const int* in_sizes, int n_in,
                              void* d_out, int out_size)
{
    const float* x      = (const float*)d_in[0];
    const float* W_emb  = (const float*)d_in[1];
    const float* b_emb  = (const float*)d_in[2];
    const float* ln1g   = (const float*)d_in[3];
    const float* ln1b   = (const float*)d_in[4];
    const float* Wqkv   = (const float*)d_in[5];
    const float* Wo     = (const float*)d_in[6];
    const float* bo     = (const float*)d_in[7];
    const float* ln2g   = (const float*)d_in[8];
    const float* ln2b   = (const float*)d_in[9];
    const float* W1     = (const float*)d_in[10];
    const float* b1     = (const float*)d_in[11];
    const float* W2     = (const float*)d_in[12];
    const float* b2     = (const float*)d_in[13];
    const float* c1W    = (const float*)d_in[14];
    const float* c1b    = (const float*)d_in[15];
    const float* bn1g   = (const float*)d_in[16];
    const float* bn1b   = (const float*)d_in[17];
    const float* bn1rm  = (const float*)d_in[18];
    const float* bn1rv  = (const float*)d_in[19];
    const float* c2W    = (const float*)d_in[20];
    const float* c2b    = (const float*)d_in[21];
    const float* bn2g   = (const float*)d_in[22];
    const float* bn2b   = (const float*)d_in[23];
    const float* bn2rm  = (const float*)d_in[24];
    const float* bn2rv  = (const float*)d_in[25];
    const float* c3W    = (const float*)d_in[26];
    const float* c3b    = (const float*)d_in[27];

    float *h, *u, *qkv, *att, *mlp, *S, *Wc, *pd1, *pd2, *psc;
    cudaGetSymbolAddress((void**)&h,   g_h);
    cudaGetSymbolAddress((void**)&u,   g_u);
    cudaGetSymbolAddress((void**)&qkv, g_qkv);
    cudaGetSymbolAddress((void**)&att, g_att);
    cudaGetSymbolAddress((void**)&mlp, g_mlp);
    cudaGetSymbolAddress((void**)&S,   g_S);
    cudaGetSymbolAddress((void**)&Wc,  g_Wc);
    cudaGetSymbolAddress((void**)&pd1, g_d1);
    cudaGetSymbolAddress((void**)&pd2, g_d2);
    cudaGetSymbolAddress((void**)&psc, g_sc);

    prep_w_kernel<<<(3 * 1024 * 512 + 255) / 256, 256>>>(W_emb, Wc);
    conv_embed<<<dim3(4, 640), 256>>>(x, Wc, b_emb, h);

    for (int l = 0; l < 2; l++) {
        long wOff = (long)l * 512 * 512;
        // LN1 -> u
        layernorm_k<<<81920 / 8, 256>>>(h, u, ln1g + l * 512, ln1b + l * 512);
        // qkv = u @ Wqkv
        sgemm_nn<<<dim3(12, 640, 1), 256>>>(u, Wqkv + (long)l * 512 * 1536, nullptr, qkv,
                                            512, 512, 1536, 1536, 0, 0, 0, 0, 0, 0);
        // S = QK^T * scale  (batched 1280)
        attn_scores<<<dim3(2, 2, 1280), 256>>>(qkv, S);
        softmax_rows<<<(1280 * 256) / 8, 256>>>(S);
        // att = P @ V (batched, pv-mode offsets)
        sgemm_nn<<<dim3(1, 2, 1280), 256>>>(S, qkv, nullptr, att,
                                            256, 256, 1536, 512, 0, 0, 0, 0, 0, 1);
        // h += att @ Wo + bo
        sgemm_nn<<<dim3(4, 640, 1), 256>>>(att, Wo + wOff, bo + l * 512, h,
                                           512, 512, 512, 512, 0, 0, 0, 1, 0, 0);
        // LN2 -> u
        layernorm_k<<<81920 / 8, 256>>>(h, u, ln2g + l * 512, ln2b + l * 512);
        // mlp = gelu(u @ W1 + b1)
        sgemm_nn<<<dim3(4, 640, 1), 256>>>(u, W1 + wOff, b1 + l * 512, mlp,
                                           512, 512, 512, 512, 0, 0, 0, 0, 2, 0);
        // h += mlp @ W2 + b2
        sgemm_nn<<<dim3(4, 640, 1), 256>>>(mlp, W2 + wOff, b2 + l * 512, h,
                                           512, 512, 512, 512, 0, 0, 0, 1, 0, 0);
    }

    head_kernel<<<81920 / 8, 256>>>(h, c1W, c1b, bn1g, bn1b, bn1rm, bn1rv,
                                    c2W, c2b, bn2g, bn2b, bn2rm, bn2rv,
                                    c3W, c3b, pd1, pd2, psc);
    final_kernel<<<32, 256>>>(pd1, pd2, psc, (float*)d_out);
}

// round 3
// speedup vs baseline: 2.2328x; 2.2328x over previous
#include <cuda_runtime.h>
#include <math.h>
#include <stdint.h>

// ==================== constants ====================
#define FULLMASK 0xffffffffu
static const float EPS_F  = 1e-5f;
static const float ATT_SCALE = 0.08838834764831845f;  // 128^-0.5

// ==================== scratch (device globals) ====================
__device__ float g_h  [81920L*512];
__device__ float g_u  [81920L*512];
__device__ float g_qkv[81920L*1536];
__device__ float g_att[81920L*512];
__device__ float g_mlp[81920L*512];
__device__ float g_S  [1280L*256*256];
__device__ float g_Vt [1280L*128*256];
__device__ float g_WtC  [512L*3072];
__device__ float g_WtQKV[2L*1536*512];
__device__ float g_WtWo [2L*512*512];
__device__ float g_WtW1 [2L*512*512];
__device__ float g_WtW2 [2L*512*512];
__device__ float g_d1 [81920];
__device__ float g_d2 [81920];
__device__ float g_sc [81920];

// ==================== helpers ====================
__device__ __forceinline__ uint32_t smem_u32(const void* p) {
    uint32_t a;
    asm("{ .reg .u64 t; cvta.to.shared.u64 t, %1; cvt.u32.u64 %0, t; }" : "=r"(a) : "l"(p));
    return a;
}
__device__ __forceinline__ void cp16(uint32_t dst, const void* src, int sz) {
    asm volatile("cp.async.cg.shared.global [%0], [%1], 16, %2;"
                 :: "r"(dst), "l"(src), "r"(sz));
}
#define CP_COMMIT() asm volatile("cp.async.commit_group;" ::: "memory")
#define CP_WAIT(N)  asm volatile("cp.async.wait_group %0;" :: "n"(N) : "memory")

__device__ __forceinline__ uint32_t f2tf32(float f) {
    uint32_t r; asm("cvt.rna.tf32.f32 %0, %1;" : "=r"(r) : "f"(f)); return r;
}
__device__ __forceinline__ void mma_tf32(float* c, const uint32_t* a, const uint32_t* b) {
    asm volatile("mma.sync.aligned.m16n8k8.row.col.f32.tf32.tf32.f32 "
        "{%0,%1,%2,%3}, {%4,%5,%6,%7}, {%8,%9}, {%0,%1,%2,%3};"
        : "+f"(c[0]), "+f"(c[1]), "+f"(c[2]), "+f"(c[3])
        : "r"(a[0]), "r"(a[1]), "r"(a[2]), "r"(a[3]), "r"(b[0]), "r"(b[1]));
}

__device__ __forceinline__ float gelu_exact(float v) {
    return 0.5f * v * (1.0f + erff(v * 0.70710678118654752f));
}
__device__ __forceinline__ float warp_sum(float v) {
    #pragma unroll
    for (int o = 16; o > 0; o >>= 1) v += __shfl_xor_sync(FULLMASK, v, o);
    return v;
}
__device__ __forceinline__ float warp_max(float v) {
    #pragma unroll
    for (int o = 16; o > 0; o >>= 1) v = fmaxf(v, __shfl_xor_sync(FULLMASK, v, o));
    return v;
}

// ==================== tf32 mma.sync GEMM ====================
// C[M,N] = act( scale*(A @ B^T) + bias + Cin ); A:[M,K] K-major, B:[N,K] K-major.
// CTA tile 128x128, 8 warps (4 m x 2 n), warp tile 32x64, K-stage 32, double buffer.
// MODE 0: generic.  MODE 1: conv 3-tap shifted K.  MODE 2: attn scores. MODE 3: PV.
#define KB 32
#define LDP 36                       // padded row length (floats)
#define ATILE (128 * LDP)            // floats per A tile
#define STAGEF (2 * ATILE)           // floats per stage (A + B)
#define SMEM_BYTES (2 * STAGEF * 4)  // 73728 bytes

template<int MODE>
__global__ void __launch_bounds__(256) tc_gemm(
    const float* __restrict__ A, const float* __restrict__ B,
    const float* __restrict__ bias, const float* __restrict__ Cin,
    float* __restrict__ C,
    int K, int lda, int ldb, int ldc,
    long sA, long sB, long sC, int act, float scale)
{
    extern __shared__ float dsm[];
    uint32_t smem0 = smem_u32(dsm);

    int tid = threadIdx.x, lane = tid & 31, wid = tid >> 5;
    int wm = wid & 3, wn = wid >> 2;
    int z = blockIdx.z;
    int m0 = blockIdx.y * 128, n0 = blockIdx.x * 128;

    long oA, oB, oC;
    if (MODE == 0) { oA = (long)z * sA; oB = (long)z * sB; oC = (long)z * sC; }
    else if (MODE == 1) { oA = 0; oB = 0; oC = 0; }
    else if (MODE == 2) {
        int bn = z >> 2, hd = z & 3;
        oA = (long)bn * (256L * 1536) + hd * 128;
        oB = oA + 512;
        oC = (long)z * 65536;
    } else {  // MODE 3: A=P [256,256], B=Vt [128,256], C=att +head*128
        int bn = z >> 2, hd = z & 3;
        oA = (long)z * 65536;
        oB = (long)z * (128L * 256);
        oC = (long)bn * (256L * 512) + hd * 128;
    }

    const float* Ab = A + oA + (long)m0 * lda;
    const float* Bb = B + oB + (long)n0 * ldb;

    float acc[2][8][4];
    #pragma unroll
    for (int mi = 0; mi < 2; mi++)
        #pragma unroll
        for (int ni = 0; ni < 8; ni++)
            #pragma unroll
            for (int q = 0; q < 4; q++) acc[mi][ni][q] = 0.f;

    int nIter = K / KB;

    // ---- tile loader (cp.async): stage s, k offset k0 ----
    auto load_stage = [&](int s, int k0) {
        uint32_t base = smem0 + s * (STAGEF * 4);
        #pragma unroll
        for (int j = 0; j < 4; j++) {
            int i = j * 256 + tid;
            int row = i >> 3, k4 = i & 7;
            uint32_t d = base + (uint32_t)(row * (LDP * 4) + k4 * 16);
            if (MODE == 1) {
                int tap = k0 >> 10;
                int kk = (k0 & 1023) + k4 * 4;
                long grow = (long)m0 + row;
                int t = (int)(grow & 255);
                int sz = ((unsigned)(t + tap - 1) < 256u) ? 16 : 0;
                const float* src = A + (grow + (tap - 1)) * 1024 + kk;
                if (!sz) src = A;
                cp16(d, src, sz);
            } else {
                cp16(d, Ab + (long)row * lda + k0 + k4 * 4, 16);
            }
        }
        #pragma unroll
        for (int j = 0; j < 4; j++) {
            int i = j * 256 + tid;
            int row = i >> 3, k4 = i & 7;
            uint32_t d = base + (uint32_t)(ATILE * 4) + (uint32_t)(row * (LDP * 4) + k4 * 16);
            cp16(d, Bb + (long)row * ldb + k0 + k4 * 4, 16);
        }
        CP_COMMIT();
    };

    load_stage(0, 0);

    for (int it = 0; it < nIter; ++it) {
        if (it + 1 < nIter) { load_stage((it + 1) & 1, (it + 1) * KB); CP_WAIT(1); }
        else                { CP_WAIT(0); }
        __syncthreads();

        const float* As = dsm + (it & 1) * STAGEF;
        const float* Bs = As + ATILE;
        const float* Ar = As + (wm * 32 + (lane >> 2)) * LDP;
        const float* Br = Bs + (wn * 64 + (lane >> 2)) * LDP;
        int kl = lane & 3;

        #pragma unroll
        for (int kc = 0; kc < 4; kc++) {
            int k = kc * 8 + kl;
            uint32_t af[2][4], bf[8][2];
            #pragma unroll
            for (int mi = 0; mi < 2; mi++) {
                const float* p = Ar + mi * 16 * LDP;
                af[mi][0] = f2tf32(p[k]);
                af[mi][1] = f2tf32(p[8 * LDP + k]);
                af[mi][2] = f2tf32(p[k + 4]);
                af[mi][3] = f2tf32(p[8 * LDP + k + 4]);
            }
            #pragma unroll
            for (int ni = 0; ni < 8; ni++) {
                const float* p = Br + ni * 8 * LDP;
                bf[ni][0] = f2tf32(p[k]);
                bf[ni][1] = f2tf32(p[k + 4]);
            }
            #pragma unroll
            for (int mi = 0; mi < 2; mi++)
                #pragma unroll
                for (int ni = 0; ni < 8; ni++)
                    mma_tf32(acc[mi][ni], af[mi], bf[ni]);
        }
        __syncthreads();
    }

    // ---- epilogue ----
    float* Cp = C + oC;
    const float* Cr = Cin ? (Cin + oC) : nullptr;
    #pragma unroll
    for (int mi = 0; mi < 2; mi++) {
        #pragma unroll
        for (int half = 0; half < 2; half++) {
            int r = m0 + wm * 32 + mi * 16 + (lane >> 2) + half * 8;
            #pragma unroll
            for (int ni = 0; ni < 8; ni++) {
                int c = n0 + wn * 64 + ni * 8 + 2 * (lane & 3);
                float v0 = acc[mi][ni][half * 2 + 0] * scale;
                float v1 = acc[mi][ni][half * 2 + 1] * scale;
                if (bias) { v0 += bias[c]; v1 += bias[c + 1]; }
                if (Cr) {
                    const float* p = Cr + (long)r * ldc + c;
                    v0 += p[0]; v1 += p[1];
                }
                if (act == 1) { v0 = fmaxf(v0, 0.f); v1 = fmaxf(v1, 0.f); }
                else if (act == 2) { v0 = gelu_exact(v0); v1 = gelu_exact(v1); }
                *(float2*)&Cp[(long)r * ldc + c] = make_float2(v0, v1);
            }
        }
    }
}

// ==================== prep / transpose kernels ====================
__global__ void prep_wc(const float* __restrict__ W, float* __restrict__ out) {
    int i = blockIdx.x * 256 + threadIdx.x;
    if (i >= 512 * 3072) return;
    int r = i % 3072, c = i / 3072;
    int tap = r >> 10, d = r & 1023;
    out[i] = W[c * 3072 + d * 3 + tap];
}
__global__ void trans_w(const float* __restrict__ in, float* __restrict__ out, int K, int N) {
    long i = (long)blockIdx.x * 256 + threadIdx.x;
    if (i >= (long)K * N) return;
    int n = (int)(i % N);
    long k = i / N;
    out[(long)n * K + k] = in[i];
}
__global__ void trans_v(const float* __restrict__ qkv, float* __restrict__ Vt) {
    __shared__ float tile[32][33];
    int z = blockIdx.z;
    int bn = z >> 2, h = z & 3;
    int d0 = blockIdx.x * 32, t0 = blockIdx.y * 32;
    int tx = threadIdx.x, ty = threadIdx.y;
    const float* src = qkv + (long)bn * (256L * 1536) + 1024 + h * 128;
    #pragma unroll
    for (int j = 0; j < 32; j += 8)
        tile[ty + j][tx] = src[(long)(t0 + ty + j) * 1536 + d0 + tx];
    __syncthreads();
    float* dst = Vt + (long)z * (128L * 256);
    #pragma unroll
    for (int j = 0; j < 32; j += 8)
        dst[(long)(d0 + ty + j) * 256 + t0 + tx] = tile[tx][ty + j];
}

// ==================== elementwise kernels ====================
__global__ __launch_bounds__(256) void softmax_rows(float* __restrict__ S) {
    long row = (long)blockIdx.x * 8 + (threadIdx.x >> 5);
    int lane = threadIdx.x & 31;
    float* p = S + row * 256 + lane * 8;
    float4 v0 = *(float4*)p;
    float4 v1 = *(float4*)(p + 4);
    float m = fmaxf(fmaxf(fmaxf(v0.x, v0.y), fmaxf(v0.z, v0.w)),
                    fmaxf(fmaxf(v1.x, v1.y), fmaxf(v1.z, v1.w)));
    m = warp_max(m);
    v0.x = __expf(v0.x - m); v0.y = __expf(v0.y - m);
    v0.z = __expf(v0.z - m); v0.w = __expf(v0.w - m);
    v1.x = __expf(v1.x - m); v1.y = __expf(v1.y - m);
    v1.z = __expf(v1.z - m); v1.w = __expf(v1.w - m);
    float s = v0.x + v0.y + v0.z + v0.w + v1.x + v1.y + v1.z + v1.w;
    s = warp_sum(s);
    float inv = 1.0f / s;
    v0.x *= inv; v0.y *= inv; v0.z *= inv; v0.w *= inv;
    v1.x *= inv; v1.y *= inv; v1.z *= inv; v1.w *= inv;
    *(float4*)p = v0;
    *(float4*)(p + 4) = v1;
}

__global__ __launch_bounds__(256) void layernorm_k(
    const float* __restrict__ in, float* __restrict__ out,
    const float* __restrict__ g, const float* __restrict__ b)
{
    long row = (long)blockIdx.x * 8 + (threadIdx.x >> 5);
    int lane = threadIdx.x & 31;
    const float* p = in + row * 512;
    float4 v[4];
    float s = 0.f, sq = 0.f;
    #pragma unroll
    for (int i = 0; i < 4; i++) {
        v[i] = *(const float4*)(p + i * 128 + lane * 4);
        s += v[i].x + v[i].y + v[i].z + v[i].w;
        sq = fmaf(v[i].x, v[i].x, sq); sq = fmaf(v[i].y, v[i].y, sq);
        sq = fmaf(v[i].z, v[i].z, sq); sq = fmaf(v[i].w, v[i].w, sq);
    }
    s = warp_sum(s); sq = warp_sum(sq);
    float mu = s * (1.0f / 512.0f);
    float var = sq * (1.0f / 512.0f) - mu * mu;
    float inv = rsqrtf(var + EPS_F);
    float* q = out + row * 512;
    #pragma unroll
    for (int i = 0; i < 4; i++) {
        int c = i * 128 + lane * 4;
        float4 gg = *(const float4*)(g + c);
        float4 bb = *(const float4*)(b + c);
        float4 o;
        o.x = (v[i].x - mu) * inv * gg.x + bb.x;
        o.y = (v[i].y - mu) * inv * gg.y + bb.y;
        o.z = (v[i].z - mu) * inv * gg.z + bb.z;
        o.w = (v[i].w - mu) * inv * gg.w + bb.w;
        *(float4*)(q + c) = o;
    }
}

__global__ __launch_bounds__(256) void head_kernel(
    const float* __restrict__ h,
    const float* __restrict__ c1W, const float* __restrict__ c1b,
    const float* __restrict__ bn1g, const float* __restrict__ bn1b,
    const float* __restrict__ bn1rm, const float* __restrict__ bn1rv,
    const float* __restrict__ c2W, const float* __restrict__ c2b,
    const float* __restrict__ bn2g, const float* __restrict__ bn2b,
    const float* __restrict__ bn2rm, const float* __restrict__ bn2rv,
    const float* __restrict__ c3W, const float* __restrict__ c3b,
    float* __restrict__ d1, float* __restrict__ d2, float* __restrict__ sc)
{
    long row = (long)blockIdx.x * 8 + (threadIdx.x >> 5);
    int lane = threadIdx.x & 31;
    const float* hr = h + row * 512;
    const float* w = c1W + lane * 512;
    float acc1 = 0.f;
    #pragma unroll 4
    for (int c0 = 0; c0 < 512; c0 += 4) {
        float4 hv = *(const float4*)(hr + c0);
        float4 wv = *(const float4*)(w + c0);
        acc1 = fmaf(hv.x, wv.x, acc1); acc1 = fmaf(hv.y, wv.y, acc1);
        acc1 = fmaf(hv.z, wv.z, acc1); acc1 = fmaf(hv.w, wv.w, acc1);
    }
    float x1 = acc1 + c1b[lane];

    float rm1 = bn1rm[lane], rv1 = bn1rv[lane];
    float dd1 = (x1 - rm1) * (x1 - rm1) / rv1;
    dd1 = warp_sum(dd1);
    float y1 = fmaxf((x1 - rm1) * rsqrtf(rv1 + EPS_F) * bn1g[lane] + bn1b[lane], 0.f);

    float acc2 = (lane < 16) ? c2b[lane] : 0.f;
    #pragma unroll
    for (int i = 0; i < 32; i++) {
        float y1i = __shfl_sync(FULLMASK, y1, i);
        float w2 = (lane < 16) ? c2W[lane * 32 + i] : 0.f;
        acc2 = fmaf(y1i, w2, acc2);
    }
    float x2 = acc2;

    float rm2 = (lane < 16) ? bn2rm[lane] : 0.f;
    float rv2 = (lane < 16) ? bn2rv[lane] : 1.f;
    float dd2 = (lane < 16) ? (x2 - rm2) * (x2 - rm2) / rv2 : 0.f;
    dd2 = warp_sum(dd2);

    float y2 = 0.f;
    if (lane < 16)
        y2 = fmaxf((x2 - rm2) * rsqrtf(rv2 + EPS_F) * bn2g[lane] + bn2b[lane], 0.f);
    float sp = (lane < 16) ? y2 * c3W[lane] : 0.f;
    sp = warp_sum(sp);
    float score = 1.0f / (1.0f + __expf(-(sp + c3b[0])));

    if (lane == 0) {
        d1[row] = sqrtf(dd1);
        d2[row] = sqrtf(dd2);
        sc[row] = score;
    }
}

__global__ void final_kernel(const float* __restrict__ d1, const float* __restrict__ d2,
                             const float* __restrict__ sc, float* __restrict__ out)
{
    int idx = blockIdx.x * blockDim.x + threadIdx.x;
    if (idx >= 8192) return;
    int b = idx >> 8, t = idx & 255;
    float s1 = 0.f, s2 = 0.f, s3 = 0.f;
    #pragma unroll
    for (int n = 0; n < 10; n++) {
        long m = ((long)(b * 10 + n)) * 256 + t;
        s1 += d1[m]; s2 += d2[m]; s3 += sc[m];
    }
    out[idx] = (s1 + s2) * 0.1f * (s3 * 0.1f);
}

// ==================== launch ====================
extern "C" void kernel_launch(void* const* d_in, const int* in_sizes, int n_in,
                              void* d_out, int out_size)
{
    const float* x      = (const float*)d_in[0];
    const float* W_emb  = (const float*)d_in[1];
    const float* b_emb  = (const float*)d_in[2];
    const float* ln1g   = (const float*)d_in[3];
    const float* ln1b   = (const float*)d_in[4];
    const float* Wqkv   = (const float*)d_in[5];
    const float* Wo     = (const float*)d_in[6];
    const float* bo     = (const float*)d_in[7];
    const float* ln2g   = (const float*)d_in[8];
    const float* ln2b   = (const float*)d_in[9];
    const float* W1     = (const float*)d_in[10];
    const float* b1     = (const float*)d_in[11];
    const float* W2     = (const float*)d_in[12];
    const float* b2     = (const float*)d_in[13];
    const float* c1W    = (const float*)d_in[14];
    const float* c1b    = (const float*)d_in[15];
    const float* bn1g   = (const float*)d_in[16];
    const float* bn1b   = (const float*)d_in[17];
    const float* bn1rm  = (const float*)d_in[18];
    const float* bn1rv  = (const float*)d_in[19];
    const float* c2W    = (const float*)d_in[20];
    const float* c2b    = (const float*)d_in[21];
    const float* bn2g   = (const float*)d_in[22];
    const float* bn2b   = (const float*)d_in[23];
    const float* bn2rm  = (const float*)d_in[24];
    const float* bn2rv  = (const float*)d_in[25];
    const float* c3W    = (const float*)d_in[26];
    const float* c3b    = (const float*)d_in[27];

    float *h, *u, *qkv, *att, *mlp, *S, *Vt, *WtC, *WtQKV, *WtWo, *WtW1, *WtW2, *pd1, *pd2, *psc;
    cudaGetSymbolAddress((void**)&h,     g_h);
    cudaGetSymbolAddress((void**)&u,     g_u);
    cudaGetSymbolAddress((void**)&qkv,   g_qkv);
    cudaGetSymbolAddress((void**)&att,   g_att);
    cudaGetSymbolAddress((void**)&mlp,   g_mlp);
    cudaGetSymbolAddress((void**)&S,     g_S);
    cudaGetSymbolAddress((void**)&Vt,    g_Vt);
    cudaGetSymbolAddress((void**)&WtC,   g_WtC);
    cudaGetSymbolAddress((void**)&WtQKV, g_WtQKV);
    cudaGetSymbolAddress((void**)&WtWo,  g_WtWo);
    cudaGetSymbolAddress((void**)&WtW1,  g_WtW1);
    cudaGetSymbolAddress((void**)&WtW2,  g_WtW2);
    cudaGetSymbolAddress((void**)&pd1,   g_d1);
    cudaGetSymbolAddress((void**)&pd2,   g_d2);
    cudaGetSymbolAddress((void**)&psc,   g_sc);

    cudaFuncSetAttribute(tc_gemm<0>, cudaFuncAttributeMaxDynamicSharedMemorySize, SMEM_BYTES);
    cudaFuncSetAttribute(tc_gemm<1>, cudaFuncAttributeMaxDynamicSharedMemorySize, SMEM_BYTES);
    cudaFuncSetAttribute(tc_gemm<2>, cudaFuncAttributeMaxDynamicSharedMemorySize, SMEM_BYTES);
    cudaFuncSetAttribute(tc_gemm<3>, cudaFuncAttributeMaxDynamicSharedMemorySize, SMEM_BYTES);

    // ---- weight prep ----
    prep_wc<<<(512 * 3072 + 255) / 256, 256>>>(W_emb, WtC);
    for (int l = 0; l < 2; l++) {
        trans_w<<<(512 * 1536 + 255) / 256, 256>>>(Wqkv + (long)l * 512 * 1536,
                                                   WtQKV + (long)l * 1536 * 512, 512, 1536);
        trans_w<<<(512 * 512 + 255) / 256, 256>>>(Wo + (long)l * 512 * 512,
                                                  WtWo + (long)l * 512 * 512, 512, 512);
        trans_w<<<(512 * 512 + 255) / 256, 256>>>(W1 + (long)l * 512 * 512,
                                                  WtW1 + (long)l * 512 * 512, 512, 512);
        trans_w<<<(512 * 512 + 255) / 256, 256>>>(W2 + (long)l * 512 * 512,
                                                  WtW2 + (long)l * 512 * 512, 512, 512);
    }

    // ---- conv embed: h = relu(x (*) W + b) via 3-tap shifted-K GEMM ----
    tc_gemm<1><<<dim3(4, 640, 1), 256, SMEM_BYTES>>>(
        x, WtC, b_emb, nullptr, h, 3072, 1024, 3072, 512, 0, 0, 0, 1, 1.0f);

    for (int l = 0; l < 2; l++) {
        long wOff = (long)l * 512 * 512;
        layernorm_k<<<81920 / 8, 256>>>(h, u, ln1g + l * 512, ln1b + l * 512);
        // qkv = u @ Wqkv
        tc_gemm<0><<<dim3(12, 640, 1), 256, SMEM_BYTES>>>(
            u, WtQKV + (long)l * 1536 * 512, nullptr, nullptr, qkv,
            512, 512, 512, 1536, 0, 0, 0, 0, 1.0f);
        // S = Q K^T * scale
        tc_gemm<2><<<dim3(2, 2, 1280), 256, SMEM_BYTES>>>(
            qkv, qkv, nullptr, nullptr, S,
            128, 1536, 1536, 256, 0, 0, 0, 0, ATT_SCALE);
        softmax_rows<<<(1280 * 256) / 8, 256>>>(S);
        trans_v<<<dim3(4, 8, 1280), dim3(32, 8)>>>(qkv, Vt);
        // att = P @ V
        tc_gemm<3><<<dim3(1, 2, 1280), 256, SMEM_BYTES>>>(
            S, Vt, nullptr, nullptr, att,
            256, 256, 256, 512, 0, 0, 0, 0, 1.0f);
        // h += att @ Wo + bo
        tc_gemm<0><<<dim3(4, 640, 1), 256, SMEM_BYTES>>>(
            att, WtWo + wOff, bo + l * 512, h, h,
            512, 512, 512, 512, 0, 0, 0, 0, 1.0f);
        layernorm_k<<<81920 / 8, 256>>>(h, u, ln2g + l * 512, ln2b + l * 512);
        // mlp = gelu(u @ W1 + b1)
        tc_gemm<0><<<dim3(4, 640, 1), 256, SMEM_BYTES>>>(
            u, WtW1 + wOff, b1 + l * 512, nullptr, mlp,
            512, 512, 512, 512, 0, 0, 0, 2, 1.0f);
        // h += mlp @ W2 + b2
        tc_gemm<0><<<dim3(4, 640, 1), 256, SMEM_BYTES>>>(
            mlp, WtW2 + wOff, b2 + l * 512, h, h,
            512, 512, 512, 512, 0, 0, 0, 0, 1.0f);
    }

    head_kernel<<<81920 / 8, 256>>>(h, c1W, c1b, bn1g, bn1b, bn1rm, bn1rv,
                                    c2W, c2b, bn2g, bn2b, bn2rm, bn2rv,
                                    c3W, c3b, pd1, pd2, psc);
    final_kernel<<<32, 256>>>(pd1, pd2, psc, (float*)d_out);
}

// round 5
// speedup vs baseline: 3.9241x; 1.7575x over previous
#include <cuda_runtime.h>
#include <cuda_fp16.h>
#include <math.h>
#include <stdint.h>

// ==================== constants ====================
#define FULLMASK 0xffffffffu
static const float EPS_F  = 1e-5f;
static const float ATT_SCALE = 0.08838834764831845f;  // 128^-0.5

// ==================== scratch (device globals) ====================
__device__ __half g_x16 [81920L*1024];
__device__ float  g_h   [81920L*512];
__device__ __half g_u16 [81920L*512];
__device__ __half g_qkv [81920L*1536];
__device__ __half g_att [81920L*512];
__device__ __half g_mlp [81920L*512];
__device__ __half g_S   [1280L*256*256];
__device__ __half g_Vt  [1280L*128*256];
__device__ __half g_WtC [512L*3072];
__device__ __half g_WtQKV[2L*1536*512];
__device__ __half g_WtWo [2L*512*512];
__device__ __half g_WtW1 [2L*512*512];
__device__ __half g_WtW2 [2L*512*512];
__device__ float  g_d1 [81920];
__device__ float  g_d2 [81920];
__device__ float  g_sc [81920];

// ==================== helpers ====================
__device__ __forceinline__ uint32_t smem_u32(const void* p) {
    uint32_t a;
    asm("{ .reg .u64 t; cvta.to.shared.u64 t, %1; cvt.u32.u64 %0, t; }" : "=r"(a) : "l"(p));
    return a;
}
__device__ __forceinline__ void cp16(uint32_t dst, const void* src, int sz) {
    asm volatile("cp.async.cg.shared.global [%0], [%1], 16, %2;"
                 :: "r"(dst), "l"(src), "r"(sz));
}
#define CP_COMMIT() asm volatile("cp.async.commit_group;" ::: "memory")
#define CP_WAIT(N)  asm volatile("cp.async.wait_group %0;" :: "n"(N) : "memory")

__device__ __forceinline__ void mma_f16(float* c, const uint32_t* a, const uint32_t* b) {
    asm volatile("mma.sync.aligned.m16n8k16.row.col.f32.f16.f16.f32 "
        "{%0,%1,%2,%3}, {%4,%5,%6,%7}, {%8,%9}, {%0,%1,%2,%3};"
        : "+f"(c[0]), "+f"(c[1]), "+f"(c[2]), "+f"(c[3])
        : "r"(a[0]), "r"(a[1]), "r"(a[2]), "r"(a[3]), "r"(b[0]), "r"(b[1]));
}

__device__ __forceinline__ float gelu_exact(float v) {
    return 0.5f * v * (1.0f + erff(v * 0.70710678118654752f));
}
__device__ __forceinline__ float warp_sum(float v) {
    #pragma unroll
    for (int o = 16; o > 0; o >>= 1) v += __shfl_xor_sync(FULLMASK, v, o);
    return v;
}
__device__ __forceinline__ float warp_max(float v) {
    #pragma unroll
    for (int o = 16; o > 0; o >>= 1) v = fmaxf(v, __shfl_xor_sync(FULLMASK, v, o));
    return v;
}

// ==================== fp16 mma.sync GEMM ====================
// C[M,N] = act( scale*(A @ B^T) + bias + Cin )
// A:[M,K] K-major fp16, B:[N,K] K-major fp16. CTA 128x128, 8 warps (4m x 2n),
// warp tile 32x64, K-chunk 64 halfs, double-buffered cp.async.
// smem: 128B rows (64 halfs), 16B-granule XOR swizzle: slot = g ^ (row&7).
// MODE 0 generic, 1 conv 3-tap shifted K, 2 attn scores, 3 PV.
// OUTH 1 -> write fp16 to Ch; else fp32 to C.
#define KB 64
#define STAGE_B 32768                 // bytes per stage (A 16K + B 16K)
#define SMEM_BYTES (2 * STAGE_B)

template<int MODE, int OUTH>
__global__ void __launch_bounds__(256) tc_gemm(
    const __half* __restrict__ A, const __half* __restrict__ B,
    const float* __restrict__ bias, const float* __restrict__ Cin,
    float* __restrict__ C, __half* __restrict__ Ch,
    int K, int lda, int ldb, int ldc,
    long sA, long sB, long sC, int act, float scale)
{
    extern __shared__ char dsm[];
    uint32_t smem0 = smem_u32(dsm);
    const uint32_t* su = (const uint32_t*)dsm;

    int tid = threadIdx.x, lane = tid & 31, wid = tid >> 5;
    int wm = wid & 3, wn = wid >> 2;
    int r_ = lane >> 2, kl = lane & 3;
    int z = blockIdx.z;
    int m0 = blockIdx.y * 128, n0 = blockIdx.x * 128;

    long oA, oB, oC;
    if (MODE == 0) { oA = (long)z * sA; oB = (long)z * sB; oC = (long)z * sC; }
    else if (MODE == 1) { oA = 0; oB = 0; oC = 0; }
    else if (MODE == 2) {
        int bn = z >> 2, hd = z & 3;
        oA = (long)bn * (256L * 1536) + hd * 128;
        oB = oA + 512;
        oC = (long)z * 65536;
    } else {  // MODE 3
        int bn = z >> 2, hd = z & 3;
        oA = (long)z * 65536;
        oB = (long)z * (128L * 256);
        oC = (long)bn * (256L * 512) + hd * 128;
    }

    const __half* Ab = A + oA + (long)m0 * lda;
    const __half* Bb = B + oB + (long)n0 * ldb;

    float acc[2][8][4];
    #pragma unroll
    for (int mi = 0; mi < 2; mi++)
        #pragma unroll
        for (int ni = 0; ni < 8; ni++)
            #pragma unroll
            for (int q = 0; q < 4; q++) acc[mi][ni][q] = 0.f;

    int nIter = K / KB;

    auto load_stage = [&](int s, int k0) {
        uint32_t base = smem0 + s * STAGE_B;
        #pragma unroll
        for (int j = 0; j < 4; j++) {
            int i = j * 256 + tid;
            int row = i >> 3, g = i & 7;
            uint32_t d = base + (uint32_t)(row * 128 + ((g ^ (row & 7)) * 16));
            if (MODE == 1) {
                int tap = k0 >> 10;
                int kk = (k0 & 1023) + g * 8;
                long grow = (long)m0 + row;
                int t = (int)(grow & 255);
                int sz = ((unsigned)(t + tap - 1) < 256u) ? 16 : 0;
                const __half* src = A + (grow + (tap - 1)) * 1024 + kk;
                if (!sz) src = A;
                cp16(d, src, sz);
            } else {
                cp16(d, Ab + (long)row * lda + k0 + g * 8, 16);
            }
        }
        #pragma unroll
        for (int j = 0; j < 4; j++) {
            int i = j * 256 + tid;
            int row = i >> 3, g = i & 7;
            uint32_t d = base + 16384u + (uint32_t)(row * 128 + ((g ^ (row & 7)) * 16));
            cp16(d, Bb + (long)row * ldb + k0 + g * 8, 16);
        }
        CP_COMMIT();
    };

    load_stage(0, 0);

    for (int it = 0; it < nIter; ++it) {
        if (it + 1 < nIter) { load_stage((it + 1) & 1, (it + 1) * KB); CP_WAIT(1); }
        else                { CP_WAIT(0); }
        __syncthreads();

        int abase = (it & 1) * (STAGE_B / 4);       // b32 units
        int bbase = abase + 4096;

        #pragma unroll
        for (int s4 = 0; s4 < 4; s4++) {            // four k16 steps per chunk
            int g0 = s4 * 2, g1 = g0 + 1;
            int x0 = ((g0 ^ r_) << 2) + kl;         // swizzled b32 column, low 8 k-halfs
            int x1 = ((g1 ^ r_) << 2) + kl;         // high 8 k-halfs
            uint32_t af[2][4], bf[8][2];
            #pragma unroll
            for (int mi = 0; mi < 2; mi++) {
                int r0 = (wm * 32 + mi * 16 + r_) * 32;
                af[mi][0] = su[abase + r0 + x0];
                af[mi][1] = su[abase + r0 + 256 + x0];   // +8 rows
                af[mi][2] = su[abase + r0 + x1];
                af[mi][3] = su[abase + r0 + 256 + x1];
            }
            #pragma unroll
            for (int ni = 0; ni < 8; ni++) {
                int c0 = (wn * 64 + ni * 8 + r_) * 32;
                bf[ni][0] = su[bbase + c0 + x0];
                bf[ni][1] = su[bbase + c0 + x1];
            }
            #pragma unroll
            for (int mi = 0; mi < 2; mi++)
                #pragma unroll
                for (int ni = 0; ni < 8; ni++)
                    mma_f16(acc[mi][ni], af[mi], bf[ni]);
        }
        __syncthreads();
    }

    // ---- epilogue ----
    const float* Cr = Cin ? (Cin + oC) : nullptr;
    #pragma unroll
    for (int mi = 0; mi < 2; mi++) {
        #pragma unroll
        for (int half_ = 0; half_ < 2; half_++) {
            int r = m0 + wm * 32 + mi * 16 + r_ + half_ * 8;
            #pragma unroll
            for (int ni = 0; ni < 8; ni++) {
                int c = n0 + wn * 64 + ni * 8 + 2 * kl;
                float v0 = acc[mi][ni][half_ * 2 + 0] * scale;
                float v1 = acc[mi][ni][half_ * 2 + 1] * scale;
                if (bias) { v0 += bias[c]; v1 += bias[c + 1]; }
                if (Cr) {
                    const float* p = Cr + (long)r * ldc + c;
                    v0 += p[0]; v1 += p[1];
                }
                if (act == 1) { v0 = fmaxf(v0, 0.f); v1 = fmaxf(v1, 0.f); }
                else if (act == 2) { v0 = gelu_exact(v0); v1 = gelu_exact(v1); }
                if (OUTH) {
                    *(__half2*)&Ch[oC + (long)r * ldc + c] =
                        __float22half2_rn(make_float2(v0, v1));
                } else {
                    *(float2*)&C[oC + (long)r * ldc + c] = make_float2(v0, v1);
                }
            }
        }
    }
}

// ==================== prep / convert kernels ====================
__global__ void f2h_kernel(const float* __restrict__ in, __half* __restrict__ out) {
    long i = ((long)blockIdx.x * 256 + threadIdx.x) * 8;
    float4 a = *(const float4*)(in + i);
    float4 b = *(const float4*)(in + i + 4);
    __half2 h[4];
    h[0] = __float22half2_rn(make_float2(a.x, a.y));
    h[1] = __float22half2_rn(make_float2(a.z, a.w));
    h[2] = __float22half2_rn(make_float2(b.x, b.y));
    h[3] = __float22half2_rn(make_float2(b.z, b.w));
    *(uint2*)(out + i)     = *(uint2*)&h[0];
    *(uint2*)(out + i + 4) = *(uint2*)&h[2];
}
// WtC16[c][tap*1024+d] = W_emb[c][d][tap]
__global__ void prep_wc(const float* __restrict__ W, __half* __restrict__ out) {
    int i = blockIdx.x * 256 + threadIdx.x;
    if (i >= 512 * 3072) return;
    int r = i % 3072, c = i / 3072;
    int tap = r >> 10, d = r & 1023;
    out[i] = __float2half(W[c * 3072 + d * 3 + tap]);
}
// out[n*K+k] = in[k*N+n]
__global__ void trans_w(const float* __restrict__ in, __half* __restrict__ out, int K, int N) {
    long i = (long)blockIdx.x * 256 + threadIdx.x;
    if (i >= (long)K * N) return;
    int n = (int)(i % N);
    long k = i / N;
    out[(long)n * K + k] = __float2half(in[i]);
}
// Vt[z][d][t] = qkv[bn][t][1024 + h*128 + d]
__global__ void trans_v(const __half* __restrict__ qkv, __half* __restrict__ Vt) {
    __shared__ __half tile[32][33];
    int z = blockIdx.z;
    int bn = z >> 2, h = z & 3;
    int d0 = blockIdx.x * 32, t0 = blockIdx.y * 32;
    int tx = threadIdx.x, ty = threadIdx.y;
    const __half* src = qkv + (long)bn * (256L * 1536) + 1024 + h * 128;
    #pragma unroll
    for (int j = 0; j < 32; j += 8)
        tile[ty + j][tx] = src[(long)(t0 + ty + j) * 1536 + d0 + tx];
    __syncthreads();
    __half* dst = Vt + (long)z * (128L * 256);
    #pragma unroll
    for (int j = 0; j < 32; j += 8)
        dst[(long)(d0 + ty + j) * 256 + t0 + tx] = tile[tx][ty + j];
}

// ==================== elementwise kernels ====================
__global__ __launch_bounds__(256) void softmax_rows(__half* __restrict__ S) {
    long row = (long)blockIdx.x * 8 + (threadIdx.x >> 5);
    int lane = threadIdx.x & 31;
    __half* p = S + row * 256 + lane * 8;
    uint2 raw0 = *(uint2*)p;
    uint2 raw1 = *(uint2*)(p + 4);
    __half2* hp0 = (__half2*)&raw0;
    __half2* hp1 = (__half2*)&raw1;
    float v[8];
    float2 f;
    f = __half22float2(hp0[0]); v[0] = f.x; v[1] = f.y;
    f = __half22float2(hp0[1]); v[2] = f.x; v[3] = f.y;
    f = __half22float2(hp1[0]); v[4] = f.x; v[5] = f.y;
    f = __half22float2(hp1[1]); v[6] = f.x; v[7] = f.y;
    float m = v[0];
    #pragma unroll
    for (int i = 1; i < 8; i++) m = fmaxf(m, v[i]);
    m = warp_max(m);
    float s = 0.f;
    #pragma unroll
    for (int i = 0; i < 8; i++) { v[i] = __expf(v[i] - m); s += v[i]; }
    s = warp_sum(s);
    float inv = 1.0f / s;
    hp0[0] = __float22half2_rn(make_float2(v[0] * inv, v[1] * inv));
    hp0[1] = __float22half2_rn(make_float2(v[2] * inv, v[3] * inv));
    hp1[0] = __float22half2_rn(make_float2(v[4] * inv, v[5] * inv));
    hp1[1] = __float22half2_rn(make_float2(v[6] * inv, v[7] * inv));
    *(uint2*)p = raw0;
    *(uint2*)(p + 4) = raw1;
}

// LN: fp32 in -> fp16 out
__global__ __launch_bounds__(256) void layernorm_k(
    const float* __restrict__ in, __half* __restrict__ out,
    const float* __restrict__ g, const float* __restrict__ b)
{
    long row = (long)blockIdx.x * 8 + (threadIdx.x >> 5);
    int lane = threadIdx.x & 31;
    const float* p = in + row * 512;
    float4 v[4];
    float s = 0.f, sq = 0.f;
    #pragma unroll
    for (int i = 0; i < 4; i++) {
        v[i] = *(const float4*)(p + i * 128 + lane * 4);
        s += v[i].x + v[i].y + v[i].z + v[i].w;
        sq = fmaf(v[i].x, v[i].x, sq); sq = fmaf(v[i].y, v[i].y, sq);
        sq = fmaf(v[i].z, v[i].z, sq); sq = fmaf(v[i].w, v[i].w, sq);
    }
    s = warp_sum(s); sq = warp_sum(sq);
    float mu = s * (1.0f / 512.0f);
    float var = sq * (1.0f / 512.0f) - mu * mu;
    float inv = rsqrtf(var + EPS_F);
    __half* q = out + row * 512;
    #pragma unroll
    for (int i = 0; i < 4; i++) {
        int c = i * 128 + lane * 4;
        float4 gg = *(const float4*)(g + c);
        float4 bb = *(const float4*)(b + c);
        float o0 = (v[i].x - mu) * inv * gg.x + bb.x;
        float o1 = (v[i].y - mu) * inv * gg.y + bb.y;
        float o2 = (v[i].z - mu) * inv * gg.z + bb.z;
        float o3 = (v[i].w - mu) * inv * gg.w + bb.w;
        __half2 h0 = __float22half2_rn(make_float2(o0, o1));
        __half2 h1 = __float22half2_rn(make_float2(o2, o3));
        *(uint2*)(q + c) = make_uint2(*(uint32_t*)&h0, *(uint32_t*)&h1);
    }
}

__global__ __launch_bounds__(256) void head_kernel(
    const float* __restrict__ h,
    const float* __restrict__ c1W, const float* __restrict__ c1b,
    const float* __restrict__ bn1g, const float* __restrict__ bn1b,
    const float* __restrict__ bn1rm, const float* __restrict__ bn1rv,
    const float* __restrict__ c2W, const float* __restrict__ c2b,
    const float* __restrict__ bn2g, const float* __restrict__ bn2b,
    const float* __restrict__ bn2rm, const float* __restrict__ bn2rv,
    const float* __restrict__ c3W, const float* __restrict__ c3b,
    float* __restrict__ d1, float* __restrict__ d2, float* __restrict__ sc)
{
    long row = (long)blockIdx.x * 8 + (threadIdx.x >> 5);
    int lane = threadIdx.x & 31;
    const float* hr = h + row * 512;
    const float* w = c1W + lane * 512;
    float acc1 = 0.f;
    #pragma unroll 4
    for (int c0 = 0; c0 < 512; c0 += 4) {
        float4 hv = *(const float4*)(hr + c0);
        float4 wv = *(const float4*)(w + c0);
        acc1 = fmaf(hv.x, wv.x, acc1); acc1 = fmaf(hv.y, wv.y, acc1);
        acc1 = fmaf(hv.z, wv.z, acc1); acc1 = fmaf(hv.w, wv.w, acc1);
    }
    float x1 = acc1 + c1b[lane];

    float rm1 = bn1rm[lane], rv1 = bn1rv[lane];
    float dd1 = (x1 - rm1) * (x1 - rm1) / rv1;
    dd1 = warp_sum(dd1);
    float y1 = fmaxf((x1 - rm1) * rsqrtf(rv1 + EPS_F) * bn1g[lane] + bn1b[lane], 0.f);

    float acc2 = (lane < 16) ? c2b[lane] : 0.f;
    #pragma unroll
    for (int i = 0; i < 32; i++) {
        float y1i = __shfl_sync(FULLMASK, y1, i);
        float w2 = (lane < 16) ? c2W[lane * 32 + i] : 0.f;
        acc2 = fmaf(y1i, w2, acc2);
    }
    float x2 = acc2;

    float rm2 = (lane < 16) ? bn2rm[lane] : 0.f;
    float rv2 = (lane < 16) ? bn2rv[lane] : 1.f;
    float dd2 = (lane < 16) ? (x2 - rm2) * (x2 - rm2) / rv2 : 0.f;
    dd2 = warp_sum(dd2);

    float y2 = 0.f;
    if (lane < 16)
        y2 = fmaxf((x2 - rm2) * rsqrtf(rv2 + EPS_F) * bn2g[lane] + bn2b[lane], 0.f);
    float sp = (lane < 16) ? y2 * c3W[lane] : 0.f;
    sp = warp_sum(sp);
    float score = 1.0f / (1.0f + __expf(-(sp + c3b[0])));

    if (lane == 0) {
        d1[row] = sqrtf(dd1);
        d2[row] = sqrtf(dd2);
        sc[row] = score;
    }
}

__global__ void final_kernel(const float* __restrict__ d1, const float* __restrict__ d2,
                             const float* __restrict__ sc, float* __restrict__ out)
{
    int idx = blockIdx.x * blockDim.x + threadIdx.x;
    if (idx >= 8192) return;
    int b = idx >> 8, t = idx & 255;
    float s1 = 0.f, s2 = 0.f, s3 = 0.f;
    #pragma unroll
    for (int n = 0; n < 10; n++) {
        long m = ((long)(b * 10 + n)) * 256 + t;
        s1 += d1[m]; s2 += d2[m]; s3 += sc[m];
    }
    out[idx] = (s1 + s2) * 0.1f * (s3 * 0.1f);
}

// ==================== launch ====================
extern "C" void kernel_launch(void* const* d_in, const int* in_sizes, int n_in,
                              void* d_out, int out_size)
{
    const float* x      = (const float*)d_in[0];
    const float* W_emb  = (const float*)d_in[1];
    const float* b_emb  = (const float*)d_in[2];
    const float* ln1g   = (const float*)d_in[3];
    const float* ln1b   = (const float*)d_in[4];
    const float* Wqkv   = (const float*)d_in[5];
    const float* Wo     = (const float*)d_in[6];
    const float* bo     = (const float*)d_in[7];
    const float* ln2g   = (const float*)d_in[8];
    const float* ln2b   = (const float*)d_in[9];
    const float* W1     = (const float*)d_in[10];
    const float* b1     = (const float*)d_in[11];
    const float* W2     = (const float*)d_in[12];
    const float* b2     = (const float*)d_in[13];
    const float* c1W    = (const float*)d_in[14];
    const float* c1b    = (const float*)d_in[15];
    const float* bn1g   = (const float*)d_in[16];
    const float* bn1b   = (const float*)d_in[17];
    const float* bn1rm  = (const float*)d_in[18];
    const float* bn1rv  = (const float*)d_in[19];
    const float* c2W    = (const float*)d_in[20];
    const float* c2b    = (const float*)d_in[21];
    const float* bn2g   = (const float*)d_in[22];
    const float* bn2b   = (const float*)d_in[23];
    const float* bn2rm  = (const float*)d_in[24];
    const float* bn2rv  = (const float*)d_in[25];
    const float* c3W    = (const float*)d_in[26];
    const float* c3b    = (const float*)d_in[27];

    __half *x16, *u16, *qkv, *att, *mlp, *S, *Vt, *WtC, *WtQKV, *WtWo, *WtW1, *WtW2;
    float *h, *pd1, *pd2, *psc;
    cudaGetSymbolAddress((void**)&x16,   g_x16);
    cudaGetSymbolAddress((void**)&h,     g_h);
    cudaGetSymbolAddress((void**)&u16,   g_u16);
    cudaGetSymbolAddress((void**)&qkv,   g_qkv);
    cudaGetSymbolAddress((void**)&att,   g_att);
    cudaGetSymbolAddress((void**)&mlp,   g_mlp);
    cudaGetSymbolAddress((void**)&S,     g_S);
    cudaGetSymbolAddress((void**)&Vt,    g_Vt);
    cudaGetSymbolAddress((void**)&WtC,   g_WtC);
    cudaGetSymbolAddress((void**)&WtQKV, g_WtQKV);
    cudaGetSymbolAddress((void**)&WtWo,  g_WtWo);
    cudaGetSymbolAddress((void**)&WtW1,  g_WtW1);
    cudaGetSymbolAddress((void**)&WtW2,  g_WtW2);
    cudaGetSymbolAddress((void**)&pd1,   g_d1);
    cudaGetSymbolAddress((void**)&pd2,   g_d2);
    cudaGetSymbolAddress((void**)&psc,   g_sc);

    cudaFuncSetAttribute(tc_gemm<0,0>, cudaFuncAttributeMaxDynamicSharedMemorySize, SMEM_BYTES);
    cudaFuncSetAttribute(tc_gemm<0,1>, cudaFuncAttributeMaxDynamicSharedMemorySize, SMEM_BYTES);
    cudaFuncSetAttribute(tc_gemm<1,0>, cudaFuncAttributeMaxDynamicSharedMemorySize, SMEM_BYTES);
    cudaFuncSetAttribute(tc_gemm<2,1>, cudaFuncAttributeMaxDynamicSharedMemorySize, SMEM_BYTES);
    cudaFuncSetAttribute(tc_gemm<3,1>, cudaFuncAttributeMaxDynamicSharedMemorySize, SMEM_BYTES);

    // ---- input + weight conversion ----
    f2h_kernel<<<40960, 256>>>(x, x16);                          // 81920*1024
    prep_wc<<<6144, 256>>>(W_emb, WtC);
    for (int l = 0; l < 2; l++) {
        trans_w<<<3072, 256>>>(Wqkv + (long)l * 512 * 1536, WtQKV + (long)l * 1536 * 512, 512, 1536);
        trans_w<<<1024, 256>>>(Wo + (long)l * 512 * 512, WtWo + (long)l * 512 * 512, 512, 512);
        trans_w<<<1024, 256>>>(W1 + (long)l * 512 * 512, WtW1 + (long)l * 512 * 512, 512, 512);
        trans_w<<<1024, 256>>>(W2 + (long)l * 512 * 512, WtW2 + (long)l * 512 * 512, 512, 512);
    }

    // ---- conv embed: h = relu(x (*) W + b), fp32 out ----
    tc_gemm<1,0><<<dim3(4, 640, 1), 256, SMEM_BYTES>>>(
        x16, WtC, b_emb, nullptr, h, nullptr, 3072, 1024, 3072, 512, 0, 0, 0, 1, 1.0f);

    for (int l = 0; l < 2; l++) {
        long wOff = (long)l * 512 * 512;
        layernorm_k<<<10240, 256>>>(h, u16, ln1g + l * 512, ln1b + l * 512);
        // qkv = u @ Wqkv  (fp16 out)
        tc_gemm<0,1><<<dim3(12, 640, 1), 256, SMEM_BYTES>>>(
            u16, WtQKV + (long)l * 1536 * 512, nullptr, nullptr, nullptr, qkv,
            512, 512, 512, 1536, 0, 0, 0, 0, 1.0f);
        // S = Q K^T * scale  (fp16 out)
        tc_gemm<2,1><<<dim3(2, 2, 1280), 256, SMEM_BYTES>>>(
            qkv, qkv, nullptr, nullptr, nullptr, S,
            128, 1536, 1536, 256, 0, 0, 0, 0, ATT_SCALE);
        softmax_rows<<<40960, 256>>>(S);
        trans_v<<<dim3(4, 8, 1280), dim3(32, 8)>>>(qkv, Vt);
        // att = P @ V  (fp16 out)
        tc_gemm<3,1><<<dim3(1, 2, 1280), 256, SMEM_BYTES>>>(
            S, Vt, nullptr, nullptr, nullptr, att,
            256, 256, 256, 512, 0, 0, 0, 0, 1.0f);
        // h += att @ Wo + bo  (fp32 residual)
        tc_gemm<0,0><<<dim3(4, 640, 1), 256, SMEM_BYTES>>>(
            att, WtWo + wOff, bo + l * 512, h, h, nullptr,
            512, 512, 512, 512, 0, 0, 0, 0, 1.0f);
        layernorm_k<<<10240, 256>>>(h, u16, ln2g + l * 512, ln2b + l * 512);
        // mlp = gelu(u @ W1 + b1)  (fp16 out)
        tc_gemm<0,1><<<dim3(4, 640, 1), 256, SMEM_BYTES>>>(
            u16, WtW1 + wOff, b1 + l * 512, nullptr, nullptr, mlp,
            512, 512, 512, 512, 0, 0, 0, 2, 1.0f);
        // h += mlp @ W2 + b2  (fp32 residual)
        tc_gemm<0,0><<<dim3(4, 640, 1), 256, SMEM_BYTES>>>(
            mlp, WtW2 + wOff, b2 + l * 512, h, h, nullptr,
            512, 512, 512, 512, 0, 0, 0, 0, 1.0f);
    }

    head_kernel<<<10240, 256>>>(h, c1W, c1b, bn1g, bn1b, bn1rm, bn1rv,
                                c2W, c2b, bn2g, bn2b, bn2rm, bn2rv,
                                c3W, c3b, pd1, pd2, psc);
    final_kernel<<<32, 256>>>(pd1, pd2, psc, (float*)d_out);
}

// round 6
// speedup vs baseline: 4.1209x; 1.0502x over previous
#include <cuda_runtime.h>
#include <cuda_fp16.h>
#include <math.h>
#include <stdint.h>

// ==================== constants ====================
#define FULLMASK 0xffffffffu
static const float EPS_F  = 1e-5f;
static const float ATT_SCALE = 0.08838834764831845f;  // 128^-0.5

// ==================== scratch (device globals) ====================
__device__ __half g_x16 [81920L*1024];
__device__ float  g_h   [81920L*512];
__device__ __half g_u16 [81920L*512];
__device__ __half g_qkv [81920L*1536];
__device__ __half g_att [81920L*512];
__device__ __half g_mlp [81920L*512];
__device__ __half g_S   [1280L*256*256];
__device__ __half g_Vt  [1280L*128*256];
__device__ __half g_WtC [512L*3072];
__device__ __half g_WtQKV[2L*1536*512];
__device__ __half g_WtWo [2L*512*512];
__device__ __half g_WtW1 [2L*512*512];
__device__ __half g_WtW2 [2L*512*512];
__device__ float  g_d1 [81920];
__device__ float  g_d2 [81920];
__device__ float  g_sc [81920];

// ==================== helpers ====================
__device__ __forceinline__ uint32_t smem_u32(const void* p) {
    uint32_t a;
    asm("{ .reg .u64 t; cvta.to.shared.u64 t, %1; cvt.u32.u64 %0, t; }" : "=r"(a) : "l"(p));
    return a;
}
__device__ __forceinline__ void cp16(uint32_t dst, const void* src, int sz) {
    asm volatile("cp.async.cg.shared.global [%0], [%1], 16, %2;"
                 :: "r"(dst), "l"(src), "r"(sz));
}
#define CP_COMMIT() asm volatile("cp.async.commit_group;" ::: "memory")
#define CP_WAIT(N)  asm volatile("cp.async.wait_group %0;" :: "n"(N) : "memory")

#define LDSM4(R, addr) \
    asm volatile("ldmatrix.sync.aligned.m8n8.x4.shared.b16 {%0,%1,%2,%3}, [%4];" \
        : "=r"((R)[0]), "=r"((R)[1]), "=r"((R)[2]), "=r"((R)[3]) : "r"(addr))

__device__ __forceinline__ void mma_f16(float* c, const uint32_t* a, uint32_t b0, uint32_t b1) {
    asm volatile("mma.sync.aligned.m16n8k16.row.col.f32.f16.f16.f32 "
        "{%0,%1,%2,%3}, {%4,%5,%6,%7}, {%8,%9}, {%0,%1,%2,%3};"
        : "+f"(c[0]), "+f"(c[1]), "+f"(c[2]), "+f"(c[3])
        : "r"(a[0]), "r"(a[1]), "r"(a[2]), "r"(a[3]), "r"(b0), "r"(b1));
}

__device__ __forceinline__ float gelu_exact(float v) {
    return 0.5f * v * (1.0f + erff(v * 0.70710678118654752f));
}
__device__ __forceinline__ float warp_sum(float v) {
    #pragma unroll
    for (int o = 16; o > 0; o >>= 1) v += __shfl_xor_sync(FULLMASK, v, o);
    return v;
}
__device__ __forceinline__ float warp_max(float v) {
    #pragma unroll
    for (int o = 16; o > 0; o >>= 1) v = fmaxf(v, __shfl_xor_sync(FULLMASK, v, o));
    return v;
}

// ==================== fp16 mma.sync GEMM (ldmatrix fragments) ====================
// C[M,N] = act( scale*(A @ B^T) + bias + Cin )
// A:[M,K] K-major fp16, B:[N,K] K-major fp16. CTA 128x128, 8 warps (4m x 2n),
// warp tile 32x64, K-chunk 64 halfs, double-buffered cp.async.
// smem rows: 128 B (64 halfs), XOR swizzle on 16B granules: slot = g ^ (row&7).
#define KB 64
#define STAGE_B 32768
#define SMEM_BYTES (2 * STAGE_B)

template<int MODE, int OUTH>
__global__ void __launch_bounds__(256, 2) tc_gemm(
    const __half* __restrict__ A, const __half* __restrict__ B,
    const float* __restrict__ bias, const float* __restrict__ Cin,
    float* __restrict__ C, __half* __restrict__ Ch,
    int K, int lda, int ldb, int ldc,
    long sA, long sB, long sC, int act, float scale)
{
    extern __shared__ char dsm[];
    uint32_t smem0 = smem_u32(dsm);

    int tid = threadIdx.x, lane = tid & 31, wid = tid >> 5;
    int wm = wid & 3, wn = wid >> 2;
    int r_ = lane >> 2, kl = lane & 3;
    int z = blockIdx.z;
    int m0 = blockIdx.y * 128, n0 = blockIdx.x * 128;

    long oA, oB, oC;
    if (MODE == 0) { oA = (long)z * sA; oB = (long)z * sB; oC = (long)z * sC; }
    else if (MODE == 1) { oA = 0; oB = 0; oC = 0; }
    else if (MODE == 2) {
        int bn = z >> 2, hd = z & 3;
        oA = (long)bn * (256L * 1536) + hd * 128;
        oB = oA + 512;
        oC = (long)z * 65536;
    } else {  // MODE 3
        int bn = z >> 2, hd = z & 3;
        oA = (long)z * 65536;
        oB = (long)z * (128L * 256);
        oC = (long)bn * (256L * 512) + hd * 128;
    }

    const __half* Ab = A + oA + (long)m0 * lda;
    const __half* Bb = B + oB + (long)n0 * ldb;

    float acc[2][8][4];
    #pragma unroll
    for (int mi = 0; mi < 2; mi++)
        #pragma unroll
        for (int ni = 0; ni < 8; ni++)
            #pragma unroll
            for (int q = 0; q < 4; q++) acc[mi][ni][q] = 0.f;

    int nIter = K / KB;

    auto load_stage = [&](int s, int k0) {
        uint32_t base = smem0 + s * STAGE_B;
        #pragma unroll
        for (int j = 0; j < 4; j++) {
            int i = j * 256 + tid;
            int row = i >> 3, g = i & 7;
            uint32_t d = base + (uint32_t)(row * 128 + ((g ^ (row & 7)) * 16));
            if (MODE == 1) {
                int tap = k0 >> 10;
                int kk = (k0 & 1023) + g * 8;
                long grow = (long)m0 + row;
                int t = (int)(grow & 255);
                int sz = ((unsigned)(t + tap - 1) < 256u) ? 16 : 0;
                const __half* src = A + (grow + (tap - 1)) * 1024 + kk;
                if (!sz) src = A;
                cp16(d, src, sz);
            } else {
                cp16(d, Ab + (long)row * lda + k0 + g * 8, 16);
            }
        }
        #pragma unroll
        for (int j = 0; j < 4; j++) {
            int i = j * 256 + tid;
            int row = i >> 3, g = i & 7;
            uint32_t d = base + 16384u + (uint32_t)(row * 128 + ((g ^ (row & 7)) * 16));
            cp16(d, Bb + (long)row * ldb + k0 + g * 8, 16);
        }
        CP_COMMIT();
    };

    load_stage(0, 0);

    // per-lane ldmatrix row bases (byte offsets within a stage)
    int lrow = lane & 15;
    int hi = lane >> 4, lx7 = lane & 7;
    uint32_t aRow0 = (uint32_t)((wm * 32 + lrow) * 128);
    uint32_t aRow1 = aRow0 + 16 * 128;
    uint32_t bRowBase = 16384u + (uint32_t)((wn * 64 + lrow) * 128);

    for (int it = 0; it < nIter; ++it) {
        if (it + 1 < nIter) { load_stage((it + 1) & 1, (it + 1) * KB); CP_WAIT(1); }
        else                { CP_WAIT(0); }
        __syncthreads();

        uint32_t stage = smem0 + (it & 1) * STAGE_B;

        #pragma unroll
        for (int s4 = 0; s4 < 4; s4++) {
            uint32_t col = (uint32_t)((((s4 * 2 + hi) ^ lx7)) << 4);
            uint32_t af0[4], af1[4];
            LDSM4(af0, stage + aRow0 + col);
            LDSM4(af1, stage + aRow1 + col);
            #pragma unroll
            for (int p = 0; p < 4; p++) {
                uint32_t bf[4];
                LDSM4(bf, stage + bRowBase + (uint32_t)(p * 16 * 128) + col);
                mma_f16(acc[0][2 * p + 0], af0, bf[0], bf[2]);
                mma_f16(acc[0][2 * p + 1], af0, bf[1], bf[3]);
                mma_f16(acc[1][2 * p + 0], af1, bf[0], bf[2]);
                mma_f16(acc[1][2 * p + 1], af1, bf[1], bf[3]);
            }
        }
        __syncthreads();
    }

    // ---- epilogue ----
    const float* Cr = Cin ? (Cin + oC) : nullptr;
    #pragma unroll
    for (int mi = 0; mi < 2; mi++) {
        #pragma unroll
        for (int half_ = 0; half_ < 2; half_++) {
            int r = m0 + wm * 32 + mi * 16 + r_ + half_ * 8;
            #pragma unroll
            for (int ni = 0; ni < 8; ni++) {
                int c = n0 + wn * 64 + ni * 8 + 2 * kl;
                float v0 = acc[mi][ni][half_ * 2 + 0] * scale;
                float v1 = acc[mi][ni][half_ * 2 + 1] * scale;
                if (bias) { v0 += bias[c]; v1 += bias[c + 1]; }
                if (Cr) {
                    const float* p = Cr + (long)r * ldc + c;
                    v0 += p[0]; v1 += p[1];
                }
                if (act == 1) { v0 = fmaxf(v0, 0.f); v1 = fmaxf(v1, 0.f); }
                else if (act == 2) { v0 = gelu_exact(v0); v1 = gelu_exact(v1); }
                if (OUTH) {
                    *(__half2*)&Ch[oC + (long)r * ldc + c] =
                        __float22half2_rn(make_float2(v0, v1));
                } else {
                    *(float2*)&C[oC + (long)r * ldc + c] = make_float2(v0, v1);
                }
            }
        }
    }
}

// ==================== prep / convert kernels ====================
__global__ void f2h_kernel(const float* __restrict__ in, __half* __restrict__ out) {
    long i = ((long)blockIdx.x * 256 + threadIdx.x) * 8;
    float4 a = *(const float4*)(in + i);
    float4 b = *(const float4*)(in + i + 4);
    __half2 h[4];
    h[0] = __float22half2_rn(make_float2(a.x, a.y));
    h[1] = __float22half2_rn(make_float2(a.z, a.w));
    h[2] = __float22half2_rn(make_float2(b.x, b.y));
    h[3] = __float22half2_rn(make_float2(b.z, b.w));
    *(uint2*)(out + i)     = *(uint2*)&h[0];
    *(uint2*)(out + i + 4) = *(uint2*)&h[2];
}
__global__ void prep_wc(const float* __restrict__ W, __half* __restrict__ out) {
    int i = blockIdx.x * 256 + threadIdx.x;
    if (i >= 512 * 3072) return;
    int r = i % 3072, c = i / 3072;
    int tap = r >> 10, d = r & 1023;
    out[i] = __float2half(W[c * 3072 + d * 3 + tap]);
}
__global__ void trans_w(const float* __restrict__ in, __half* __restrict__ out, int K, int N) {
    long i = (long)blockIdx.x * 256 + threadIdx.x;
    if (i >= (long)K * N) return;
    int n = (int)(i % N);
    long k = i / N;
    out[(long)n * K + k] = __float2half(in[i]);
}
__global__ void trans_v(const __half* __restrict__ qkv, __half* __restrict__ Vt) {
    __shared__ __half tile[32][33];
    int z = blockIdx.z;
    int bn = z >> 2, h = z & 3;
    int d0 = blockIdx.x * 32, t0 = blockIdx.y * 32;
    int tx = threadIdx.x, ty = threadIdx.y;
    const __half* src = qkv + (long)bn * (256L * 1536) + 1024 + h * 128;
    #pragma unroll
    for (int j = 0; j < 32; j += 8)
        tile[ty + j][tx] = src[(long)(t0 + ty + j) * 1536 + d0 + tx];
    __syncthreads();
    __half* dst = Vt + (long)z * (128L * 256);
    #pragma unroll
    for (int j = 0; j < 32; j += 8)
        dst[(long)(d0 + ty + j) * 256 + t0 + tx] = tile[tx][ty + j];
}

// ==================== elementwise kernels ====================
__global__ __launch_bounds__(256) void softmax_rows(__half* __restrict__ S) {
    long row = (long)blockIdx.x * 8 + (threadIdx.x >> 5);
    int lane = threadIdx.x & 31;
    __half* p = S + row * 256 + lane * 8;
    uint2 raw0 = *(uint2*)p;
    uint2 raw1 = *(uint2*)(p + 4);
    __half2* hp0 = (__half2*)&raw0;
    __half2* hp1 = (__half2*)&raw1;
    float v[8];
    float2 f;
    f = __half22float2(hp0[0]); v[0] = f.x; v[1] = f.y;
    f = __half22float2(hp0[1]); v[2] = f.x; v[3] = f.y;
    f = __half22float2(hp1[0]); v[4] = f.x; v[5] = f.y;
    f = __half22float2(hp1[1]); v[6] = f.x; v[7] = f.y;
    float m = v[0];
    #pragma unroll
    for (int i = 1; i < 8; i++) m = fmaxf(m, v[i]);
    m = warp_max(m);
    float s = 0.f;
    #pragma unroll
    for (int i = 0; i < 8; i++) { v[i] = __expf(v[i] - m); s += v[i]; }
    s = warp_sum(s);
    float inv = 1.0f / s;
    hp0[0] = __float22half2_rn(make_float2(v[0] * inv, v[1] * inv));
    hp0[1] = __float22half2_rn(make_float2(v[2] * inv, v[3] * inv));
    hp1[0] = __float22half2_rn(make_float2(v[4] * inv, v[5] * inv));
    hp1[1] = __float22half2_rn(make_float2(v[6] * inv, v[7] * inv));
    *(uint2*)p = raw0;
    *(uint2*)(p + 4) = raw1;
}

__global__ __launch_bounds__(256) void layernorm_k(
    const float* __restrict__ in, __half* __restrict__ out,
    const float* __restrict__ g, const float* __restrict__ b)
{
    long row = (long)blockIdx.x * 8 + (threadIdx.x >> 5);
    int lane = threadIdx.x & 31;
    const float* p = in + row * 512;
    float4 v[4];
    float s = 0.f, sq = 0.f;
    #pragma unroll
    for (int i = 0; i < 4; i++) {
        v[i] = *(const float4*)(p + i * 128 + lane * 4);
        s += v[i].x + v[i].y + v[i].z + v[i].w;
        sq = fmaf(v[i].x, v[i].x, sq); sq = fmaf(v[i].y, v[i].y, sq);
        sq = fmaf(v[i].z, v[i].z, sq); sq = fmaf(v[i].w, v[i].w, sq);
    }
    s = warp_sum(s); sq = warp_sum(sq);
    float mu = s * (1.0f / 512.0f);
    float var = sq * (1.0f / 512.0f) - mu * mu;
    float inv = rsqrtf(var + EPS_F);
    __half* q = out + row * 512;
    #pragma unroll
    for (int i = 0; i < 4; i++) {
        int c = i * 128 + lane * 4;
        float4 gg = *(const float4*)(g + c);
        float4 bb = *(const float4*)(b + c);
        float o0 = (v[i].x - mu) * inv * gg.x + bb.x;
        float o1 = (v[i].y - mu) * inv * gg.y + bb.y;
        float o2 = (v[i].z - mu) * inv * gg.z + bb.z;
        float o3 = (v[i].w - mu) * inv * gg.w + bb.w;
        __half2 h0 = __float22half2_rn(make_float2(o0, o1));
        __half2 h1 = __float22half2_rn(make_float2(o2, o3));
        *(uint2*)(q + c) = make_uint2(*(uint32_t*)&h0, *(uint32_t*)&h1);
    }
}

__global__ __launch_bounds__(256) void head_kernel(
    const float* __restrict__ h,
    const float* __restrict__ c1W, const float* __restrict__ c1b,
    const float* __restrict__ bn1g, const float* __restrict__ bn1b,
    const float* __restrict__ bn1rm, const float* __restrict__ bn1rv,
    const float* __restrict__ c2W, const float* __restrict__ c2b,
    const float* __restrict__ bn2g, const float* __restrict__ bn2b,
    const float* __restrict__ bn2rm, const float* __restrict__ bn2rv,
    const float* __restrict__ c3W, const float* __restrict__ c3b,
    float* __restrict__ d1, float* __restrict__ d2, float* __restrict__ sc)
{
    long row = (long)blockIdx.x * 8 + (threadIdx.x >> 5);
    int lane = threadIdx.x & 31;
    const float* hr = h + row * 512;
    const float* w = c1W + lane * 512;
    float acc1 = 0.f;
    #pragma unroll 4
    for (int c0 = 0; c0 < 512; c0 += 4) {
        float4 hv = *(const float4*)(hr + c0);
        float4 wv = *(const float4*)(w + c0);
        acc1 = fmaf(hv.x, wv.x, acc1); acc1 = fmaf(hv.y, wv.y, acc1);
        acc1 = fmaf(hv.z, wv.z, acc1); acc1 = fmaf(hv.w, wv.w, acc1);
    }
    float x1 = acc1 + c1b[lane];

    float rm1 = bn1rm[lane], rv1 = bn1rv[lane];
    float dd1 = (x1 - rm1) * (x1 - rm1) / rv1;
    dd1 = warp_sum(dd1);
    float y1 = fmaxf((x1 - rm1) * rsqrtf(rv1 + EPS_F) * bn1g[lane] + bn1b[lane], 0.f);

    float acc2 = (lane < 16) ? c2b[lane] : 0.f;
    #pragma unroll
    for (int i = 0; i < 32; i++) {
        float y1i = __shfl_sync(FULLMASK, y1, i);
        float w2 = (lane < 16) ? c2W[lane * 32 + i] : 0.f;
        acc2 = fmaf(y1i, w2, acc2);
    }
    float x2 = acc2;

    float rm2 = (lane < 16) ? bn2rm[lane] : 0.f;
    float rv2 = (lane < 16) ? bn2rv[lane] : 1.f;
    float dd2 = (lane < 16) ? (x2 - rm2) * (x2 - rm2) / rv2 : 0.f;
    dd2 = warp_sum(dd2);

    float y2 = 0.f;
    if (lane < 16)
        y2 = fmaxf((x2 - rm2) * rsqrtf(rv2 + EPS_F) * bn2g[lane] + bn2b[lane], 0.f);
    float sp = (lane < 16) ? y2 * c3W[lane] : 0.f;
    sp = warp_sum(sp);
    float score = 1.0f / (1.0f + __expf(-(sp + c3b[0])));

    if (lane == 0) {
        d1[row] = sqrtf(dd1);
        d2[row] = sqrtf(dd2);
        sc[row] = score;
    }
}

__global__ void final_kernel(const float* __restrict__ d1, const float* __restrict__ d2,
                             const float* __restrict__ sc, float* __restrict__ out)
{
    int idx = blockIdx.x * blockDim.x + threadIdx.x;
    if (idx >= 8192) return;
    int b = idx >> 8, t = idx & 255;
    float s1 = 0.f, s2 = 0.f, s3 = 0.f;
    #pragma unroll
    for (int n = 0; n < 10; n++) {
        long m = ((long)(b * 10 + n)) * 256 + t;
        s1 += d1[m]; s2 += d2[m]; s3 += sc[m];
    }
    out[idx] = (s1 + s2) * 0.1f * (s3 * 0.1f);
}

// ==================== launch ====================
extern "C" void kernel_launch(void* const* d_in, const int* in_sizes, int n_in,
                              void* d_out, int out_size)
{
    const float* x      = (const float*)d_in[0];
    const float* W_emb  = (const float*)d_in[1];
    const float* b_emb  = (const float*)d_in[2];
    const float* ln1g   = (const float*)d_in[3];
    const float* ln1b   = (const float*)d_in[4];
    const float* Wqkv   = (const float*)d_in[5];
    const float* Wo     = (const float*)d_in[6];
    const float* bo     = (const float*)d_in[7];
    const float* ln2g   = (const float*)d_in[8];
    const float* ln2b   = (const float*)d_in[9];
    const float* W1     = (const float*)d_in[10];
    const float* b1     = (const float*)d_in[11];
    const float* W2     = (const float*)d_in[12];
    const float* b2     = (const float*)d_in[13];
    const float* c1W    = (const float*)d_in[14];
    const float* c1b    = (const float*)d_in[15];
    const float* bn1g   = (const float*)d_in[16];
    const float* bn1b   = (const float*)d_in[17];
    const float* bn1rm  = (const float*)d_in[18];
    const float* bn1rv  = (const float*)d_in[19];
    const float* c2W    = (const float*)d_in[20];
    const float* c2b    = (const float*)d_in[21];
    const float* bn2g   = (const float*)d_in[22];
    const float* bn2b   = (const float*)d_in[23];
    const float* bn2rm  = (const float*)d_in[24];
    const float* bn2rv  = (const float*)d_in[25];
    const float* c3W    = (const float*)d_in[26];
    const float* c3b    = (const float*)d_in[27];

    __half *x16, *u16, *qkv, *att, *mlp, *S, *Vt, *WtC, *WtQKV, *WtWo, *WtW1, *WtW2;
    float *h, *pd1, *pd2, *psc;
    cudaGetSymbolAddress((void**)&x16,   g_x16);
    cudaGetSymbolAddress((void**)&h,     g_h);
    cudaGetSymbolAddress((void**)&u16,   g_u16);
    cudaGetSymbolAddress((void**)&qkv,   g_qkv);
    cudaGetSymbolAddress((void**)&att,   g_att);
    cudaGetSymbolAddress((void**)&mlp,   g_mlp);
    cudaGetSymbolAddress((void**)&S,     g_S);
    cudaGetSymbolAddress((void**)&Vt,    g_Vt);
    cudaGetSymbolAddress((void**)&WtC,   g_WtC);
    cudaGetSymbolAddress((void**)&WtQKV, g_WtQKV);
    cudaGetSymbolAddress((void**)&WtWo,  g_WtWo);
    cudaGetSymbolAddress((void**)&WtW1,  g_WtW1);
    cudaGetSymbolAddress((void**)&WtW2,  g_WtW2);
    cudaGetSymbolAddress((void**)&pd1,   g_d1);
    cudaGetSymbolAddress((void**)&pd2,   g_d2);
    cudaGetSymbolAddress((void**)&psc,   g_sc);

    cudaFuncSetAttribute(tc_gemm<0,0>, cudaFuncAttributeMaxDynamicSharedMemorySize, SMEM_BYTES);
    cudaFuncSetAttribute(tc_gemm<0,1>, cudaFuncAttributeMaxDynamicSharedMemorySize, SMEM_BYTES);
    cudaFuncSetAttribute(tc_gemm<1,0>, cudaFuncAttributeMaxDynamicSharedMemorySize, SMEM_BYTES);
    cudaFuncSetAttribute(tc_gemm<2,1>, cudaFuncAttributeMaxDynamicSharedMemorySize, SMEM_BYTES);
    cudaFuncSetAttribute(tc_gemm<3,1>, cudaFuncAttributeMaxDynamicSharedMemorySize, SMEM_BYTES);

    // ---- input + weight conversion ----
    f2h_kernel<<<40960, 256>>>(x, x16);
    prep_wc<<<6144, 256>>>(W_emb, WtC);
    for (int l = 0; l < 2; l++) {
        trans_w<<<3072, 256>>>(Wqkv + (long)l * 512 * 1536, WtQKV + (long)l * 1536 * 512, 512, 1536);
        trans_w<<<1024, 256>>>(Wo + (long)l * 512 * 512, WtWo + (long)l * 512 * 512, 512, 512);
        trans_w<<<1024, 256>>>(W1 + (long)l * 512 * 512, WtW1 + (long)l * 512 * 512, 512, 512);
        trans_w<<<1024, 256>>>(W2 + (long)l * 512 * 512, WtW2 + (long)l * 512 * 512, 512, 512);
    }

    // ---- conv embed: h = relu(x (*) W + b), fp32 out ----
    tc_gemm<1,0><<<dim3(4, 640, 1), 256, SMEM_BYTES>>>(
        x16, WtC, b_emb, nullptr, h, nullptr, 3072, 1024, 3072, 512, 0, 0, 0, 1, 1.0f);

    for (int l = 0; l < 2; l++) {
        long wOff = (long)l * 512 * 512;
        layernorm_k<<<10240, 256>>>(h, u16, ln1g + l * 512, ln1b + l * 512);
        tc_gemm<0,1><<<dim3(12, 640, 1), 256, SMEM_BYTES>>>(
            u16, WtQKV + (long)l * 1536 * 512, nullptr, nullptr, nullptr, qkv,
            512, 512, 512, 1536, 0, 0, 0, 0, 1.0f);
        tc_gemm<2,1><<<dim3(2, 2, 1280), 256, SMEM_BYTES>>>(
            qkv, qkv, nullptr, nullptr, nullptr, S,
            128, 1536, 1536, 256, 0, 0, 0, 0, ATT_SCALE);
        softmax_rows<<<40960, 256>>>(S);
        trans_v<<<dim3(4, 8, 1280), dim3(32, 8)>>>(qkv, Vt);
        tc_gemm<3,1><<<dim3(1, 2, 1280), 256, SMEM_BYTES>>>(
            S, Vt, nullptr, nullptr, nullptr, att,
            256, 256, 256, 512, 0, 0, 0, 0, 1.0f);
        tc_gemm<0,0><<<dim3(4, 640, 1), 256, SMEM_BYTES>>>(
            att, WtWo + wOff, bo + l * 512, h, h, nullptr,
            512, 512, 512, 512, 0, 0, 0, 0, 1.0f);
        layernorm_k<<<10240, 256>>>(h, u16, ln2g + l * 512, ln2b + l * 512);
        tc_gemm<0,1><<<dim3(4, 640, 1), 256, SMEM_BYTES>>>(
            u16, WtW1 + wOff, b1 + l * 512, nullptr, nullptr, mlp,
            512, 512, 512, 512, 0, 0, 0, 2, 1.0f);
        tc_gemm<0,0><<<dim3(4, 640, 1), 256, SMEM_BYTES>>>(
            mlp, WtW2 + wOff, b2 + l * 512, h, h, nullptr,
            512, 512, 512, 512, 0, 0, 0, 0, 1.0f);
    }

    head_kernel<<<10240, 256>>>(h, c1W, c1b, bn1g, bn1b, bn1rm, bn1rv,
                                c2W, c2b, bn2g, bn2b, bn2rm, bn2rv,
                                c3W, c3b, pd1, pd2, psc);
    final_kernel<<<32, 256>>>(pd1, pd2, psc, (float*)d_out);
}

// round 8
// speedup vs baseline: 4.1424x; 1.0052x over previous
#include <cuda_runtime.h>
#include <cuda_fp16.h>
#include <math.h>
#include <stdint.h>

// ==================== constants ====================
#define FULLMASK 0xffffffffu
static const float EPS_F  = 1e-5f;
static const float ATT_SCALE = 0.08838834764831845f;  // 128^-0.5

// ==================== scratch (device globals) ====================
__device__ __half g_x16 [81920L*1024];
__device__ float  g_h   [81920L*512];
__device__ __half g_u16 [81920L*512];
__device__ __half g_qkv [81920L*1536];
__device__ __half g_att [81920L*512];
__device__ __half g_mlp [81920L*512];
__device__ __half g_S   [1280L*256*256];
__device__ __half g_Vt  [1280L*128*256];
__device__ __half g_WtC [512L*3072];
__device__ __half g_WtQKV[2L*1536*512];
__device__ __half g_WtWo [2L*512*512];
__device__ __half g_WtW1 [2L*512*512];
__device__ __half g_WtW2 [2L*512*512];
__device__ float  g_d1 [81920];
__device__ float  g_d2 [81920];
__device__ float  g_sc [81920];

// ==================== helpers ====================
__device__ __forceinline__ uint32_t smem_u32(const void* p) {
    uint32_t a;
    asm("{ .reg .u64 t; cvta.to.shared.u64 t, %1; cvt.u32.u64 %0, t; }" : "=r"(a) : "l"(p));
    return a;
}
__device__ __forceinline__ void cp16(uint32_t dst, const void* src, int sz) {
    asm volatile("cp.async.cg.shared.global [%0], [%1], 16, %2;"
                 :: "r"(dst), "l"(src), "r"(sz));
}
#define CP_COMMIT() asm volatile("cp.async.commit_group;" ::: "memory")
#define CP_WAIT(N)  asm volatile("cp.async.wait_group %0;" :: "n"(N) : "memory")

#define LDSM4(R, addr) \
    asm volatile("ldmatrix.sync.aligned.m8n8.x4.shared.b16 {%0,%1,%2,%3}, [%4];" \
        : "=r"((R)[0]), "=r"((R)[1]), "=r"((R)[2]), "=r"((R)[3]) : "r"(addr))

__device__ __forceinline__ void mma_f16(float* c, const uint32_t* a, uint32_t b0, uint32_t b1) {
    asm volatile("mma.sync.aligned.m16n8k16.row.col.f32.f16.f16.f32 "
        "{%0,%1,%2,%3}, {%4,%5,%6,%7}, {%8,%9}, {%0,%1,%2,%3};"
        : "+f"(c[0]), "+f"(c[1]), "+f"(c[2]), "+f"(c[3])
        : "r"(a[0]), "r"(a[1]), "r"(a[2]), "r"(a[3]), "r"(b0), "r"(b1));
}

__device__ __forceinline__ float gelu_exact(float v) {
    return 0.5f * v * (1.0f + erff(v * 0.70710678118654752f));
}
__device__ __forceinline__ float warp_sum(float v) {
    #pragma unroll
    for (int o = 16; o > 0; o >>= 1) v += __shfl_xor_sync(FULLMASK, v, o);
    return v;
}
__device__ __forceinline__ float warp_max(float v) {
    #pragma unroll
    for (int o = 16; o > 0; o >>= 1) v = fmaxf(v, __shfl_xor_sync(FULLMASK, v, o));
    return v;
}

// ==================== fp16 mma.sync GEMM (ldmatrix, 3-stage pipeline) ====================
// C[M,N] = act( scale*(A @ B^T) + bias + Cin )
// A:[M,K] K-major fp16, B:[N,K] K-major fp16. CTA 128x128, 8 warps (4m x 2n),
// warp tile 32x64, K-chunk 64 halfs, 3-stage cp.async pipeline.
// smem rows: 128 B (64 halfs), XOR swizzle on 16B granules: slot = g ^ (row&7).
#define KB 64
#define STAGE_B 32768
#define SMEM_BYTES (3 * STAGE_B)

template<int MODE, int OUTH>
__global__ void __launch_bounds__(256, 2) tc_gemm(
    const __half* __restrict__ A, const __half* __restrict__ B,
    const float* __restrict__ bias, const float* __restrict__ Cin,
    float* __restrict__ C, __half* __restrict__ Ch,
    int K, int lda, int ldb, int ldc,
    long sA, long sB, long sC, int act, float scale)
{
    extern __shared__ char dsm[];
    uint32_t smem0 = smem_u32(dsm);

    int tid = threadIdx.x, lane = tid & 31, wid = tid >> 5;
    int wm = wid & 3, wn = wid >> 2;
    int r_ = lane >> 2, kl = lane & 3;
    int z = blockIdx.z;
    int m0 = blockIdx.y * 128, n0 = blockIdx.x * 128;

    long oA, oB, oC;
    if (MODE == 0) { oA = (long)z * sA; oB = (long)z * sB; oC = (long)z * sC; }
    else if (MODE == 1) { oA = 0; oB = 0; oC = 0; }
    else if (MODE == 2) {
        int bn = z >> 2, hd = z & 3;
        oA = (long)bn * (256L * 1536) + hd * 128;
        oB = oA + 512;
        oC = (long)z * 65536;
    } else {  // MODE 3
        int bn = z >> 2, hd = z & 3;
        oA = (long)z * 65536;
        oB = (long)z * (128L * 256);
        oC = (long)bn * (256L * 512) + hd * 128;
    }

    const __half* Ab = A + oA + (long)m0 * lda;
    const __half* Bb = B + oB + (long)n0 * ldb;

    float acc[2][8][4];
    #pragma unroll
    for (int mi = 0; mi < 2; mi++)
        #pragma unroll
        for (int ni = 0; ni < 8; ni++)
            #pragma unroll
            for (int q = 0; q < 4; q++) acc[mi][ni][q] = 0.f;

    int nIter = K / KB;

    auto load_stage = [&](int s, int k0) {
        uint32_t base = smem0 + (uint32_t)s * STAGE_B;
        #pragma unroll
        for (int j = 0; j < 4; j++) {
            int i = j * 256 + tid;
            int row = i >> 3, g = i & 7;
            uint32_t d = base + (uint32_t)(row * 128 + ((g ^ (row & 7)) * 16));
            if (MODE == 1) {
                int tap = k0 >> 10;
                int kk = (k0 & 1023) + g * 8;
                long grow = (long)m0 + row;
                int t = (int)(grow & 255);
                int sz = ((unsigned)(t + tap - 1) < 256u) ? 16 : 0;
                const __half* src = A + (grow + (tap - 1)) * 1024 + kk;
                if (!sz) src = A;
                cp16(d, src, sz);
            } else {
                cp16(d, Ab + (long)row * lda + k0 + g * 8, 16);
            }
        }
        #pragma unroll
        for (int j = 0; j < 4; j++) {
            int i = j * 256 + tid;
            int row = i >> 3, g = i & 7;
            uint32_t d = base + 16384u + (uint32_t)(row * 128 + ((g ^ (row & 7)) * 16));
            cp16(d, Bb + (long)row * ldb + k0 + g * 8, 16);
        }
        CP_COMMIT();
    };

    // prologue: fill 2 of 3 stages
    load_stage(0, 0);
    if (nIter > 1) load_stage(1, KB);

    // per-lane ldmatrix row bases (byte offsets within a stage)
    int lrow = lane & 15;
    int hi = lane >> 4, lx7 = lane & 7;
    uint32_t aRow0 = (uint32_t)((wm * 32 + lrow) * 128);
    uint32_t aRow1 = aRow0 + 16 * 128;
    uint32_t bRowBase = 16384u + (uint32_t)((wn * 64 + lrow) * 128);

    int st = 0;                         // stage index of current chunk
    for (int it = 0; it < nIter; ++it) {
        // issue stage it+2, then drain so stage `it` is ready
        if (it + 2 < nIter) {
            int s2 = st + 2; if (s2 >= 3) s2 -= 3;
            load_stage(s2, (it + 2) * KB);
            CP_WAIT(2);
        } else if (it + 1 < nIter) {
            CP_WAIT(1);
        } else {
            CP_WAIT(0);
        }
        __syncthreads();

        uint32_t stage = smem0 + (uint32_t)st * STAGE_B;

        #pragma unroll
        for (int s4 = 0; s4 < 4; s4++) {
            uint32_t col = (uint32_t)((((s4 * 2 + hi) ^ lx7)) << 4);
            uint32_t af0[4], af1[4];
            LDSM4(af0, stage + aRow0 + col);
            LDSM4(af1, stage + aRow1 + col);
            #pragma unroll
            for (int p = 0; p < 4; p++) {
                uint32_t bf[4];
                LDSM4(bf, stage + bRowBase + (uint32_t)(p * 16 * 128) + col);
                mma_f16(acc[0][2 * p + 0], af0, bf[0], bf[2]);
                mma_f16(acc[0][2 * p + 1], af0, bf[1], bf[3]);
                mma_f16(acc[1][2 * p + 0], af1, bf[0], bf[2]);
                mma_f16(acc[1][2 * p + 1], af1, bf[1], bf[3]);
            }
        }
        __syncthreads();
        if (++st == 3) st = 0;
    }

    // ---- epilogue ----
    const float* Cr = Cin ? (Cin + oC) : nullptr;
    #pragma unroll
    for (int mi = 0; mi < 2; mi++) {
        #pragma unroll
        for (int half_ = 0; half_ < 2; half_++) {
            int r = m0 + wm * 32 + mi * 16 + r_ + half_ * 8;
            #pragma unroll
            for (int ni = 0; ni < 8; ni++) {
                int c = n0 + wn * 64 + ni * 8 + 2 * kl;
                float v0 = acc[mi][ni][half_ * 2 + 0] * scale;
                float v1 = acc[mi][ni][half_ * 2 + 1] * scale;
                if (bias) { v0 += bias[c]; v1 += bias[c + 1]; }
                if (Cr) {
                    const float* p = Cr + (long)r * ldc + c;
                    v0 += p[0]; v1 += p[1];
                }
                if (act == 1) { v0 = fmaxf(v0, 0.f); v1 = fmaxf(v1, 0.f); }
                else if (act == 2) { v0 = gelu_exact(v0); v1 = gelu_exact(v1); }
                if (OUTH) {
                    *(__half2*)&Ch[oC + (long)r * ldc + c] =
                        __float22half2_rn(make_float2(v0, v1));
                } else {
                    *(float2*)&C[oC + (long)r * ldc + c] = make_float2(v0, v1);
                }
            }
        }
    }
}

// ==================== prep / convert kernels ====================
__global__ void f2h_kernel(const float* __restrict__ in, __half* __restrict__ out) {
    long i = ((long)blockIdx.x * 256 + threadIdx.x) * 8;
    float4 a = *(const float4*)(in + i);
    float4 b = *(const float4*)(in + i + 4);
    __half2 h[4];
    h[0] = __float22half2_rn(make_float2(a.x, a.y));
    h[1] = __float22half2_rn(make_float2(a.z, a.w));
    h[2] = __float22half2_rn(make_float2(b.x, b.y));
    h[3] = __float22half2_rn(make_float2(b.z, b.w));
    *(uint2*)(out + i)     = *(uint2*)&h[0];
    *(uint2*)(out + i + 4) = *(uint2*)&h[2];
}
__global__ void prep_wc(const float* __restrict__ W, __half* __restrict__ out) {
    int i = blockIdx.x * 256 + threadIdx.x;
    if (i >= 512 * 3072) return;
    int r = i % 3072, c = i / 3072;
    int tap = r >> 10, d = r & 1023;
    out[i] = __float2half(W[c * 3072 + d * 3 + tap]);
}
__global__ void trans_w(const float* __restrict__ in, __half* __restrict__ out, int K, int N) {
    long i = (long)blockIdx.x * 256 + threadIdx.x;
    if (i >= (long)K * N) return;
    int n = (int)(i % N);
    long k = i / N;
    out[(long)n * K + k] = __float2half(in[i]);
}
__global__ void trans_v(const __half* __restrict__ qkv, __half* __restrict__ Vt) {
    __shared__ __half tile[32][33];
    int z = blockIdx.z;
    int bn = z >> 2, h = z & 3;
    int d0 = blockIdx.x * 32, t0 = blockIdx.y * 32;
    int tx = threadIdx.x, ty = threadIdx.y;
    const __half* src = qkv + (long)bn * (256L * 1536) + 1024 + h * 128;
    #pragma unroll
    for (int j = 0; j < 32; j += 8)
        tile[ty + j][tx] = src[(long)(t0 + ty + j) * 1536 + d0 + tx];
    __syncthreads();
    __half* dst = Vt + (long)z * (128L * 256);
    #pragma unroll
    for (int j = 0; j < 32; j += 8)
        dst[(long)(d0 + ty + j) * 256 + t0 + tx] = tile[tx][ty + j];
}

// ==================== elementwise kernels ====================
__global__ __launch_bounds__(256) void softmax_rows(__half* __restrict__ S) {
    long row = (long)blockIdx.x * 8 + (threadIdx.x >> 5);
    int lane = threadIdx.x & 31;
    __half* p = S + row * 256 + lane * 8;
    uint2 raw0 = *(uint2*)p;
    uint2 raw1 = *(uint2*)(p + 4);
    __half2* hp0 = (__half2*)&raw0;
    __half2* hp1 = (__half2*)&raw1;
    float v[8];
    float2 f;
    f = __half22float2(hp0[0]); v[0] = f.x; v[1] = f.y;
    f = __half22float2(hp0[1]); v[2] = f.x; v[3] = f.y;
    f = __half22float2(hp1[0]); v[4] = f.x; v[5] = f.y;
    f = __half22float2(hp1[1]); v[6] = f.x; v[7] = f.y;
    float m = v[0];
    #pragma unroll
    for (int i = 1; i < 8; i++) m = fmaxf(m, v[i]);
    m = warp_max(m);
    float s = 0.f;
    #pragma unroll
    for (int i = 0; i < 8; i++) { v[i] = __expf(v[i] - m); s += v[i]; }
    s = warp_sum(s);
    float inv = 1.0f / s;
    hp0[0] = __float22half2_rn(make_float2(v[0] * inv, v[1] * inv));
    hp0[1] = __float22half2_rn(make_float2(v[2] * inv, v[3] * inv));
    hp1[0] = __float22half2_rn(make_float2(v[4] * inv, v[5] * inv));
    hp1[1] = __float22half2_rn(make_float2(v[6] * inv, v[7] * inv));
    *(uint2*)p = raw0;
    *(uint2*)(p + 4) = raw1;
}

__global__ __launch_bounds__(256) void layernorm_k(
    const float* __restrict__ in, __half* __restrict__ out,
    const float* __restrict__ g, const float* __restrict__ b)
{
    long row = (long)blockIdx.x * 8 + (threadIdx.x >> 5);
    int lane = threadIdx.x & 31;
    const float* p = in + row * 512;
    float4 v[4];
    float s = 0.f, sq = 0.f;
    #pragma unroll
    for (int i = 0; i < 4; i++) {
        v[i] = *(const float4*)(p + i * 128 + lane * 4);
        s += v[i].x + v[i].y + v[i].z + v[i].w;
        sq = fmaf(v[i].x, v[i].x, sq); sq = fmaf(v[i].y, v[i].y, sq);
        sq = fmaf(v[i].z, v[i].z, sq); sq = fmaf(v[i].w, v[i].w, sq);
    }
    s = warp_sum(s); sq = warp_sum(sq);
    float mu = s * (1.0f / 512.0f);
    float var = sq * (1.0f / 512.0f) - mu * mu;
    float inv = rsqrtf(var + EPS_F);
    __half* q = out + row * 512;
    #pragma unroll
    for (int i = 0; i < 4; i++) {
        int c = i * 128 + lane * 4;
        float4 gg = *(const float4*)(g + c);
        float4 bb = *(const float4*)(b + c);
        float o0 = (v[i].x - mu) * inv * gg.x + bb.x;
        float o1 = (v[i].y - mu) * inv * gg.y + bb.y;
        float o2 = (v[i].z - mu) * inv * gg.z + bb.z;
        float o3 = (v[i].w - mu) * inv * gg.w + bb.w;
        __half2 h0 = __float22half2_rn(make_float2(o0, o1));
        __half2 h1 = __float22half2_rn(make_float2(o2, o3));
        *(uint2*)(q + c) = make_uint2(*(uint32_t*)&h0, *(uint32_t*)&h1);
    }
}

__global__ __launch_bounds__(256) void head_kernel(
    const float* __restrict__ h,
    const float* __restrict__ c1W, const float* __restrict__ c1b,
    const float* __restrict__ bn1g, const float* __restrict__ bn1b,
    const float* __restrict__ bn1rm, const float* __restrict__ bn1rv,
    const float* __restrict__ c2W, const float* __restrict__ c2b,
    const float* __restrict__ bn2g, const float* __restrict__ bn2b,
    const float* __restrict__ bn2rm, const float* __restrict__ bn2rv,
    const float* __restrict__ c3W, const float* __restrict__ c3b,
    float* __restrict__ d1, float* __restrict__ d2, float* __restrict__ sc)
{
    long row = (long)blockIdx.x * 8 + (threadIdx.x >> 5);
    int lane = threadIdx.x & 31;
    const float* hr = h + row * 512;
    const float* w = c1W + lane * 512;
    float acc1 = 0.f;
    #pragma unroll 4
    for (int c0 = 0; c0 < 512; c0 += 4) {
        float4 hv = *(const float4*)(hr + c0);
        float4 wv = *(const float4*)(w + c0);
        acc1 = fmaf(hv.x, wv.x, acc1); acc1 = fmaf(hv.y, wv.y, acc1);
        acc1 = fmaf(hv.z, wv.z, acc1); acc1 = fmaf(hv.w, wv.w, acc1);
    }
    float x1 = acc1 + c1b[lane];

    float rm1 = bn1rm[lane], rv1 = bn1rv[lane];
    float dd1 = (x1 - rm1) * (x1 - rm1) / rv1;
    dd1 = warp_sum(dd1);
    float y1 = fmaxf((x1 - rm1) * rsqrtf(rv1 + EPS_F) * bn1g[lane] + bn1b[lane], 0.f);

    float acc2 = (lane < 16) ? c2b[lane] : 0.f;
    #pragma unroll
    for (int i = 0; i < 32; i++) {
        float y1i = __shfl_sync(FULLMASK, y1, i);
        float w2 = (lane < 16) ? c2W[lane * 32 + i] : 0.f;
        acc2 = fmaf(y1i, w2, acc2);
    }
    float x2 = acc2;

    float rm2 = (lane < 16) ? bn2rm[lane] : 0.f;
    float rv2 = (lane < 16) ? bn2rv[lane] : 1.f;
    float dd2 = (lane < 16) ? (x2 - rm2) * (x2 - rm2) / rv2 : 0.f;
    dd2 = warp_sum(dd2);

    float y2 = 0.f;
    if (lane < 16)
        y2 = fmaxf((x2 - rm2) * rsqrtf(rv2 + EPS_F) * bn2g[lane] + bn2b[lane], 0.f);
    float sp = (lane < 16) ? y2 * c3W[lane] : 0.f;
    sp = warp_sum(sp);
    float score = 1.0f / (1.0f + __expf(-(sp + c3b[0])));

    if (lane == 0) {
        d1[row] = sqrtf(dd1);
        d2[row] = sqrtf(dd2);
        sc[row] = score;
    }
}

__global__ void final_kernel(const float* __restrict__ d1, const float* __restrict__ d2,
                             const float* __restrict__ sc, float* __restrict__ out)
{
    int idx = blockIdx.x * blockDim.x + threadIdx.x;
    if (idx >= 8192) return;
    int b = idx >> 8, t = idx & 255;
    float s1 = 0.f, s2 = 0.f, s3 = 0.f;
    #pragma unroll
    for (int n = 0; n < 10; n++) {
        long m = ((long)(b * 10 + n)) * 256 + t;
        s1 += d1[m]; s2 += d2[m]; s3 += sc[m];
    }
    out[idx] = (s1 + s2) * 0.1f * (s3 * 0.1f);
}

// ==================== launch ====================
extern "C" void kernel_launch(void* const* d_in, const int* in_sizes, int n_in,
                              void* d_out, int out_size)
{
    const float* x      = (const float*)d_in[0];
    const float* W_emb  = (const float*)d_in[1];
    const float* b_emb  = (const float*)d_in[2];
    const float* ln1g   = (const float*)d_in[3];
    const float* ln1b   = (const float*)d_in[4];
    const float* Wqkv   = (const float*)d_in[5];
    const float* Wo     = (const float*)d_in[6];
    const float* bo     = (const float*)d_in[7];
    const float* ln2g   = (const float*)d_in[8];
    const float* ln2b   = (const float*)d_in[9];
    const float* W1     = (const float*)d_in[10];
    const float* b1     = (const float*)d_in[11];
    const float* W2     = (const float*)d_in[12];
    const float* b2     = (const float*)d_in[13];
    const float* c1W    = (const float*)d_in[14];
    const float* c1b    = (const float*)d_in[15];
    const float* bn1g   = (const float*)d_in[16];
    const float* bn1b   = (const float*)d_in[17];
    const float* bn1rm  = (const float*)d_in[18];
    const float* bn1rv  = (const float*)d_in[19];
    const float* c2W    = (const float*)d_in[20];
    const float* c2b    = (const float*)d_in[21];
    const float* bn2g   = (const float*)d_in[22];
    const float* bn2b   = (const float*)d_in[23];
    const float* bn2rm  = (const float*)d_in[24];
    const float* bn2rv  = (const float*)d_in[25];
    const float* c3W    = (const float*)d_in[26];
    const float* c3b    = (const float*)d_in[27];

    __half *x16, *u16, *qkv, *att, *mlp, *S, *Vt, *WtC, *WtQKV, *WtWo, *WtW1, *WtW2;
    float *h, *pd1, *pd2, *psc;
    cudaGetSymbolAddress((void**)&x16,   g_x16);
    cudaGetSymbolAddress((void**)&h,     g_h);
    cudaGetSymbolAddress((void**)&u16,   g_u16);
    cudaGetSymbolAddress((void**)&qkv,   g_qkv);
    cudaGetSymbolAddress((void**)&att,   g_att);
    cudaGetSymbolAddress((void**)&mlp,   g_mlp);
    cudaGetSymbolAddress((void**)&S,     g_S);
    cudaGetSymbolAddress((void**)&Vt,    g_Vt);
    cudaGetSymbolAddress((void**)&WtC,   g_WtC);
    cudaGetSymbolAddress((void**)&WtQKV, g_WtQKV);
    cudaGetSymbolAddress((void**)&WtWo,  g_WtWo);
    cudaGetSymbolAddress((void**)&WtW1,  g_WtW1);
    cudaGetSymbolAddress((void**)&WtW2,  g_WtW2);
    cudaGetSymbolAddress((void**)&pd1,   g_d1);
    cudaGetSymbolAddress((void**)&pd2,   g_d2);
    cudaGetSymbolAddress((void**)&psc,   g_sc);

    cudaFuncSetAttribute(tc_gemm<0,0>, cudaFuncAttributeMaxDynamicSharedMemorySize, SMEM_BYTES);
    cudaFuncSetAttribute(tc_gemm<0,1>, cudaFuncAttributeMaxDynamicSharedMemorySize, SMEM_BYTES);
    cudaFuncSetAttribute(tc_gemm<1,0>, cudaFuncAttributeMaxDynamicSharedMemorySize, SMEM_BYTES);
    cudaFuncSetAttribute(tc_gemm<2,1>, cudaFuncAttributeMaxDynamicSharedMemorySize, SMEM_BYTES);
    cudaFuncSetAttribute(tc_gemm<3,1>, cudaFuncAttributeMaxDynamicSharedMemorySize, SMEM_BYTES);

    // ---- prep (ordered so launch #6 is the QKV GEMM for ncu -s 5 -c 1) ----
    f2h_kernel<<<40960, 256>>>(x, x16);                                   // 1
    prep_wc<<<6144, 256>>>(W_emb, WtC);                                   // 2
    // conv embed: h = relu(x (*) W + b), fp32 out
    tc_gemm<1,0><<<dim3(4, 640, 1), 256, SMEM_BYTES>>>(
        x16, WtC, b_emb, nullptr, h, nullptr, 3072, 1024, 3072, 512, 0, 0, 0, 1, 1.0f);  // 3
    trans_w<<<3072, 256>>>(Wqkv, WtQKV, 512, 1536);                       // 4 (layer 0)
    layernorm_k<<<10240, 256>>>(h, u16, ln1g, ln1b);                      // 5
    tc_gemm<0,1><<<dim3(12, 640, 1), 256, SMEM_BYTES>>>(                  // 6 <- profiled
        u16, WtQKV, nullptr, nullptr, nullptr, qkv,
        512, 512, 512, 1536, 0, 0, 0, 0, 1.0f);
    // remaining weight transposes
    trans_w<<<3072, 256>>>(Wqkv + 512L * 1536, WtQKV + 1536L * 512, 512, 1536);
    for (int l = 0; l < 2; l++) {
        trans_w<<<1024, 256>>>(Wo + (long)l * 512 * 512, WtWo + (long)l * 512 * 512, 512, 512);
        trans_w<<<1024, 256>>>(W1 + (long)l * 512 * 512, WtW1 + (long)l * 512 * 512, 512, 512);
        trans_w<<<1024, 256>>>(W2 + (long)l * 512 * 512, WtW2 + (long)l * 512 * 512, 512, 512);
    }

    for (int l = 0; l < 2; l++) {
        long wOff = (long)l * 512 * 512;
        if (l > 0) {
            layernorm_k<<<10240, 256>>>(h, u16, ln1g + l * 512, ln1b + l * 512);
            tc_gemm<0,1><<<dim3(12, 640, 1), 256, SMEM_BYTES>>>(
                u16, WtQKV + (long)l * 1536 * 512, nullptr, nullptr, nullptr, qkv,
                512, 512, 512, 1536, 0, 0, 0, 0, 1.0f);
        }
        tc_gemm<2,1><<<dim3(2, 2, 1280), 256, SMEM_BYTES>>>(
            qkv, qkv, nullptr, nullptr, nullptr, S,
            128, 1536, 1536, 256, 0, 0, 0, 0, ATT_SCALE);
        softmax_rows<<<40960, 256>>>(S);
        trans_v<<<dim3(4, 8, 1280), dim3(32, 8)>>>(qkv, Vt);
        tc_gemm<3,1><<<dim3(1, 2, 1280), 256, SMEM_BYTES>>>(
            S, Vt, nullptr, nullptr, nullptr, att,
            256, 256, 256, 512, 0, 0, 0, 0, 1.0f);
        tc_gemm<0,0><<<dim3(4, 640, 1), 256, SMEM_BYTES>>>(
            att, WtWo + wOff, bo + l * 512, h, h, nullptr,
            512, 512, 512, 512, 0, 0, 0, 0, 1.0f);
        layernorm_k<<<10240, 256>>>(h, u16, ln2g + l * 512, ln2b + l * 512);
        tc_gemm<0,1><<<dim3(4, 640, 1), 256, SMEM_BYTES>>>(
            u16, WtW1 + wOff, b1 + l * 512, nullptr, nullptr, mlp,
            512, 512, 512, 512, 0, 0, 0, 2, 1.0f);
        tc_gemm<0,0><<<dim3(4, 640, 1), 256, SMEM_BYTES>>>(
            mlp, WtW2 + wOff, b2 + l * 512, h, h, nullptr,
            512, 512, 512, 512, 0, 0, 0, 0, 1.0f);
    }

    head_kernel<<<10240, 256>>>(h, c1W, c1b, bn1g, bn1b, bn1rm, bn1rv,
                                c2W, c2b, bn2g, bn2b, bn2rm, bn2rv,
                                c3W, c3b, pd1, pd2, psc);
    final_kernel<<<32, 256>>>(pd1, pd2, psc, (float*)d_out);
}